// round 1
// baseline (speedup 1.0000x reference)
#include <cuda_runtime.h>
#include <math.h>
#include <stdint.h>

// Problem shape (fixed by the dataset)
#define MB 16384   // rows (2N)
#define DD 2048    // backbone dim
#define HH 2048    // hidden dim
#define FF 128     // feature dim

__device__ __constant__ float c_dummy; // (nothing)

constexpr float INV_T = 1.0f / 0.07f;   // 14.285714...

// Scratch (static device globals — allocation-free per harness rules)
__device__ float g_h [(size_t)MB * HH];   // 128 MB  relu(features@w1+b1)
__device__ float g_p [(size_t)MB * FF];   // 8 MB    h@w2+b2
__device__ float g_z [(size_t)MB * FF];   // 8 MB    normalized
__device__ float g_zT[(size_t)FF * MB];   // 8 MB    z transposed (for coalesced sim GEMM)
__device__ float g_lse[MB];
__device__ float g_pos[MB];

// ---------------------------------------------------------------------------
// Classic fp32 SGEMM: C[M,N] = act(A[M,K] @ B[K,N] + bias[N])
// BM=BN=128, BK=8, TM=TN=8, 256 threads. M,N multiples of 128; K multiple of 8.
// ---------------------------------------------------------------------------
template<bool RELU>
__global__ __launch_bounds__(256)
void sgemm_k(const float* __restrict__ A, const float* __restrict__ B,
             const float* __restrict__ bias, float* __restrict__ C,
             int M, int N, int K)
{
    __shared__ float As[8][128];
    __shared__ float Bs[8][128];

    const int tid = threadIdx.x;
    const int bx = blockIdx.x, by = blockIdx.y;
    const int tx = tid & 15, ty = tid >> 4;
    const int aRow = tid >> 1,  aCol = (tid & 1) << 2;   // A: 128x8 tile, one float4/thread
    const int bRow = tid >> 5,  bCol = (tid & 31) << 2;  // B: 8x128 tile, one float4/thread

    const float* Aptr = A + (size_t)(by * 128 + aRow) * K + aCol;
    const float* Bptr = B + (size_t)bRow * N + bx * 128 + bCol;

    float acc[8][8];
#pragma unroll
    for (int i = 0; i < 8; i++)
#pragma unroll
        for (int j = 0; j < 8; j++) acc[i][j] = 0.f;

    for (int kt = 0; kt < K; kt += 8) {
        float4 av = *(const float4*)(Aptr + kt);
        As[aCol + 0][aRow] = av.x;
        As[aCol + 1][aRow] = av.y;
        As[aCol + 2][aRow] = av.z;
        As[aCol + 3][aRow] = av.w;
        *(float4*)&Bs[bRow][bCol] = *(const float4*)(Bptr + (size_t)kt * N);
        __syncthreads();
#pragma unroll
        for (int k = 0; k < 8; k++) {
            float ar[8], br[8];
            *(float4*)(ar)     = *(const float4*)&As[k][ty * 8];
            *(float4*)(ar + 4) = *(const float4*)&As[k][ty * 8 + 4];
            *(float4*)(br)     = *(const float4*)&Bs[k][tx * 8];
            *(float4*)(br + 4) = *(const float4*)&Bs[k][tx * 8 + 4];
#pragma unroll
            for (int i = 0; i < 8; i++)
#pragma unroll
                for (int j = 0; j < 8; j++)
                    acc[i][j] = fmaf(ar[i], br[j], acc[i][j]);
        }
        __syncthreads();
    }

    float bv[8];
    *(float4*)(bv)     = *(const float4*)&bias[bx * 128 + tx * 8];
    *(float4*)(bv + 4) = *(const float4*)&bias[bx * 128 + tx * 8 + 4];
#pragma unroll
    for (int i = 0; i < 8; i++) {
        size_t row = (size_t)by * 128 + ty * 8 + i;
        float o[8];
#pragma unroll
        for (int j = 0; j < 8; j++) {
            float v = acc[i][j] + bv[j];
            o[j] = RELU ? fmaxf(v, 0.f) : v;
        }
        *(float4*)&C[row * N + bx * 128 + tx * 8]     = *(const float4*)(o);
        *(float4*)&C[row * N + bx * 128 + tx * 8 + 4] = *(const float4*)(o + 4);
    }
}

// ---------------------------------------------------------------------------
// Row L2-normalize p -> z, write z, z^T, and z to output buffer.
// One block (128 threads) per row.
// ---------------------------------------------------------------------------
__global__ void normalize_k(const float* __restrict__ P, float* __restrict__ Z,
                            float* __restrict__ ZT, float* __restrict__ outz)
{
    const int row = blockIdx.x;
    const int t = threadIdx.x;
    float v = P[(size_t)row * FF + t];
    float s = v * v;
#pragma unroll
    for (int o = 16; o; o >>= 1) s += __shfl_xor_sync(0xffffffffu, s, o);
    __shared__ float ws[4];
    if ((t & 31) == 0) ws[t >> 5] = s;
    __syncthreads();
    float tot = ws[0] + ws[1] + ws[2] + ws[3];
    float inv = 1.0f / fmaxf(sqrtf(tot), 1e-12f);
    float z = v * inv;
    Z [(size_t)row * FF + t] = z;
    ZT[(size_t)t * MB + row] = z;
    if (outz) outz[(size_t)row * FF + t] = z;
}

// ---------------------------------------------------------------------------
// pos[i] = (z_i . z_{(i+N) mod 2N}) / T    (one block of 128 per row)
// ---------------------------------------------------------------------------
__global__ void pos_k(const float* __restrict__ Z, float* __restrict__ pos)
{
    const int row = blockIdx.x;
    const int t = threadIdx.x;
    const int prow = (row + MB / 2) & (MB - 1);
    float s = Z[(size_t)row * FF + t] * Z[(size_t)prow * FF + t];
#pragma unroll
    for (int o = 16; o; o >>= 1) s += __shfl_xor_sync(0xffffffffu, s, o);
    __shared__ float ws[4];
    if ((t & 31) == 0) ws[t >> 5] = s;
    __syncthreads();
    if (t == 0) pos[row] = (ws[0] + ws[1] + ws[2] + ws[3]) * INV_T;
}

// ---------------------------------------------------------------------------
// Streaming masked logsumexp of sim = (z z^T)/T, diagonal excluded.
// Each block owns 128 rows; loops over all 128 column tiles, computes the
// 128x128 sim tile in registers (SGEMM micro-kernel, K=128), accumulates
// exp(sim - 1/T) per row (sim <= 1/T since rows are unit-norm).
// lse[i] = log(sum) + 1/T.
// ---------------------------------------------------------------------------
__global__ __launch_bounds__(256)
void lse_k(const float* __restrict__ Z, const float* __restrict__ ZT,
           float* __restrict__ lse)
{
    __shared__ float As[8][128];
    __shared__ float Bs[8][128];

    const int tid = threadIdx.x;
    const int by = blockIdx.x;
    const int tx = tid & 15, ty = tid >> 4;
    const int aRow = tid >> 1,  aCol = (tid & 1) << 2;
    const int bRow = tid >> 5,  bCol = (tid & 31) << 2;
    const float CM = INV_T;

    float rs[8];
#pragma unroll
    for (int i = 0; i < 8; i++) rs[i] = 0.f;

    const float* Aptr = Z + (size_t)(by * 128 + aRow) * FF + aCol;

    for (int bx = 0; bx < MB / 128; bx++) {
        float acc[8][8];
#pragma unroll
        for (int i = 0; i < 8; i++)
#pragma unroll
            for (int j = 0; j < 8; j++) acc[i][j] = 0.f;

#pragma unroll
        for (int kt = 0; kt < FF; kt += 8) {
            float4 av = *(const float4*)(Aptr + kt);
            As[aCol + 0][aRow] = av.x;
            As[aCol + 1][aRow] = av.y;
            As[aCol + 2][aRow] = av.z;
            As[aCol + 3][aRow] = av.w;
            *(float4*)&Bs[bRow][bCol] =
                *(const float4*)(ZT + (size_t)(kt + bRow) * MB + bx * 128 + bCol);
            __syncthreads();
#pragma unroll
            for (int k = 0; k < 8; k++) {
                float ar[8], br[8];
                *(float4*)(ar)     = *(const float4*)&As[k][ty * 8];
                *(float4*)(ar + 4) = *(const float4*)&As[k][ty * 8 + 4];
                *(float4*)(br)     = *(const float4*)&Bs[k][tx * 8];
                *(float4*)(br + 4) = *(const float4*)&Bs[k][tx * 8 + 4];
#pragma unroll
                for (int i = 0; i < 8; i++)
#pragma unroll
                    for (int j = 0; j < 8; j++)
                        acc[i][j] = fmaf(ar[i], br[j], acc[i][j]);
            }
            __syncthreads();
        }

#pragma unroll
        for (int i = 0; i < 8; i++) {
            const int gi = by * 128 + ty * 8 + i;
#pragma unroll
            for (int j = 0; j < 8; j++) {
                const int gj = bx * 128 + tx * 8 + j;
                float e = __expf(fmaf(acc[i][j], INV_T, -CM));
                rs[i] += (gi != gj) ? e : 0.f;
            }
        }
    }

    // Reduce across the 16 lanes (same ty) sharing each row group.
#pragma unroll
    for (int i = 0; i < 8; i++) {
        float s = rs[i];
#pragma unroll
        for (int o = 8; o; o >>= 1) s += __shfl_xor_sync(0xffffffffu, s, o);
        if (tx == 0) lse[by * 128 + ty * 8 + i] = logf(s) + CM;
    }
}

// ---------------------------------------------------------------------------
// Deterministic final reduction: loss = mean(lse - pos)
// ---------------------------------------------------------------------------
__global__ void loss_k(const float* __restrict__ lse, const float* __restrict__ pos,
                       float* __restrict__ out)
{
    __shared__ float sm[256];
    const int t = threadIdx.x;
    float s = 0.f;
    for (int i = t; i < MB; i += 256) s += lse[i] - pos[i];
    sm[t] = s;
    __syncthreads();
    for (int o = 128; o; o >>= 1) {
        if (t < o) sm[t] += sm[t + o];
        __syncthreads();
    }
    if (t == 0) out[0] = sm[0] * (1.0f / MB);
}

// ---------------------------------------------------------------------------
// kernel_launch
// Inputs: features[MB,DD], w1[DD,HH], b1[HH], w2[HH,FF], b2[FF]
// Output: [loss, z (MB*FF floats, rows 0..N-1 then N..2N-1 contiguous)]
// ---------------------------------------------------------------------------
extern "C" void kernel_launch(void* const* d_in, const int* in_sizes, int n_in,
                              void* d_out, int out_size)
{
    const float* features = (const float*)d_in[0];
    const float* w1 = (const float*)d_in[1];
    const float* b1 = (const float*)d_in[2];
    const float* w2 = (const float*)d_in[3];
    const float* b2 = (const float*)d_in[4];
    float* out = (float*)d_out;

    float *h, *p, *z, *zt, *lseb, *posb;
    cudaGetSymbolAddress((void**)&h,    g_h);
    cudaGetSymbolAddress((void**)&p,    g_p);
    cudaGetSymbolAddress((void**)&z,    g_z);
    cudaGetSymbolAddress((void**)&zt,   g_zT);
    cudaGetSymbolAddress((void**)&lseb, g_lse);
    cudaGetSymbolAddress((void**)&posb, g_pos);

    // 1) h = relu(features @ w1 + b1)
    sgemm_k<true><<<dim3(HH / 128, MB / 128), 256>>>(features, w1, b1, h, MB, HH, DD);

    // 2) p = h @ w2 + b2
    sgemm_k<false><<<dim3(FF / 128, MB / 128), 256>>>(h, w2, b2, p, MB, FF, HH);

    // 3) z = normalize(p); also build z^T and write z to the output
    float* outz = (out_size >= 1 + MB * FF) ? (out + 1) : nullptr;
    normalize_k<<<MB, 128>>>(p, z, zt, outz);

    // 4) pos[i] = sim[i, (i+N)%2N]
    pos_k<<<MB, 128>>>(z, posb);

    // 5) masked row logsumexp of sim
    lse_k<<<MB / 128, 256>>>(z, zt, lseb);

    // 6) loss = mean(lse - pos)
    loss_k<<<1, 256>>>(lseb, posb, out);
}

// round 4
// speedup vs baseline: 2.4643x; 2.4643x over previous
#include <cuda_runtime.h>
#include <cuda_bf16.h>
#include <math.h>
#include <stdint.h>

#define MB 16384   // rows (2N)
#define DD 2048
#define HH 2048
#define FF 128
#define KK 2048    // K of both big GEMMs

constexpr float INV_T = 1.0f / 0.07f;

// ---------------- scratch --------------------------------------------------
__device__ __nv_bfloat16 g_fhi [(size_t)MB * DD];
__device__ __nv_bfloat16 g_flo [(size_t)MB * DD];
__device__ __nv_bfloat16 g_w1hi[(size_t)HH * DD];
__device__ __nv_bfloat16 g_w1lo[(size_t)HH * DD];
__device__ __nv_bfloat16 g_w2hi[(size_t)FF * HH];
__device__ __nv_bfloat16 g_w2lo[(size_t)FF * HH];
__device__ __nv_bfloat16 g_hhi [(size_t)MB * HH];
__device__ __nv_bfloat16 g_hlo [(size_t)MB * HH];
__device__ __nv_bfloat16 g_zhi [(size_t)MB * FF];
__device__ __nv_bfloat16 g_zlo [(size_t)MB * FF];
__device__ float g_z  [(size_t)MB * FF];
__device__ float g_lse[MB];
__device__ float g_pos[MB];

// ---------------- helpers ---------------------------------------------------
__device__ __forceinline__ uint32_t smem_u32(const void* p) {
    uint32_t a;
    asm("{ .reg .u64 t; cvta.to.shared.u64 t, %1; cvt.u32.u64 %0, t; }"
        : "=r"(a) : "l"(p));
    return a;
}
__device__ __forceinline__ void cp16(uint32_t s, const void* g) {
    asm volatile("cp.async.cg.shared.global [%0], [%1], 16;" :: "r"(s), "l"(g));
}
#define CP_COMMIT() asm volatile("cp.async.commit_group;")
#define CP_WAIT(n)  asm volatile("cp.async.wait_group %0;" :: "n"(n))

__device__ __forceinline__ void ldsm4(uint32_t* r, uint32_t a) {
    asm volatile("ldmatrix.sync.aligned.m8n8.x4.shared.b16 {%0,%1,%2,%3}, [%4];"
                 : "=r"(r[0]), "=r"(r[1]), "=r"(r[2]), "=r"(r[3]) : "r"(a));
}
__device__ __forceinline__ void mma_bf16(float* c, const uint32_t* a,
                                         uint32_t b0, uint32_t b1) {
    asm volatile(
        "mma.sync.aligned.m16n8k16.row.col.f32.bf16.bf16.f32 "
        "{%0,%1,%2,%3}, {%4,%5,%6,%7}, {%8,%9}, {%0,%1,%2,%3};"
        : "+f"(c[0]), "+f"(c[1]), "+f"(c[2]), "+f"(c[3])
        : "r"(a[0]), "r"(a[1]), "r"(a[2]), "r"(a[3]), "r"(b0), "r"(b1));
}
__device__ __forceinline__ uint32_t pack2bf(float a, float b) {
    __nv_bfloat162 t = __floats2bfloat162_rn(a, b);
    return *reinterpret_cast<uint32_t*>(&t);
}
// fast exp on FMA/ALU pipes (no MUFU): y in [-45, 0.1], abs err ~2e-6
__device__ __forceinline__ float fexp(float y) {
    float t = fmaf(y, 1.4426950408889634f, 12582912.0f);
    int ki = __float_as_int(t) - 0x4B400000;
    float k = t - 12582912.0f;
    float r = fmaf(k, -0.693359375f, y);
    r = fmaf(k, 2.12194440e-4f, r);
    float p = fmaf(r, 8.33333333e-3f, 4.16666667e-2f);
    p = fmaf(p, r, 1.66666667e-1f);
    p = fmaf(p, r, 5.0e-1f);
    p = fmaf(p, r, 1.0f);
    p = fmaf(p, r, 1.0f);
    return __int_as_float(__float_as_int(p) + (ki << 23));
}

// ---------------------------------------------------------------------------
// prep: fp32 -> bf16 (hi, lo) split; and transpose+split for weights
// ---------------------------------------------------------------------------
__global__ void split_k(const float* __restrict__ X, __nv_bfloat16* __restrict__ Hi,
                        __nv_bfloat16* __restrict__ Lo, size_t n)
{
    size_t stride = (size_t)gridDim.x * blockDim.x * 4;
    for (size_t i = ((size_t)blockIdx.x * blockDim.x + threadIdx.x) * 4; i < n; i += stride) {
        float4 v = *(const float4*)(X + i);
        float vv[4] = {v.x, v.y, v.z, v.w};
        __nv_bfloat16 h[4], l[4];
#pragma unroll
        for (int k = 0; k < 4; k++) {
            h[k] = __float2bfloat16_rn(vv[k]);
            l[k] = __float2bfloat16_rn(vv[k] - __bfloat162float(h[k]));
        }
        *(uint2*)(Hi + i) = *(uint2*)h;
        *(uint2*)(Lo + i) = *(uint2*)l;
    }
}
__global__ void tsplit_k(const float* __restrict__ W, __nv_bfloat16* __restrict__ Thi,
                         __nv_bfloat16* __restrict__ Tlo, int K, int N)
{
    __shared__ float t[32][33];
    int nx = blockIdx.x * 32, ky = blockIdx.y * 32;
    int tx = threadIdx.x, ty = threadIdx.y;   // 32 x 8
#pragma unroll
    for (int i = 0; i < 4; i++)
        t[ty + 8 * i][tx] = W[(size_t)(ky + ty + 8 * i) * N + nx + tx];
    __syncthreads();
#pragma unroll
    for (int i = 0; i < 4; i++) {
        float v = t[tx][ty + 8 * i];
        __nv_bfloat16 h = __float2bfloat16_rn(v);
        __nv_bfloat16 l = __float2bfloat16_rn(v - __bfloat162float(h));
        size_t o = (size_t)(nx + ty + 8 * i) * K + ky + tx;
        Thi[o] = h;
        Tlo[o] = l;
    }
}

// ---------------------------------------------------------------------------
// HMMA split-bf16 GEMM: C[M,N] = act(A[M,K] @ B^T + bias), B stored [N][K].
// 128x128 block, Kc=64, 8 warps (2x4 -> 64x32 warp tiles), cp.async 2-stage.
// ---------------------------------------------------------------------------
template<bool NORM>
__global__ __launch_bounds__(256)
void hgemm_k(const __nv_bfloat16* __restrict__ Ahi, const __nv_bfloat16* __restrict__ Alo,
             const __nv_bfloat16* __restrict__ Bhi, const __nv_bfloat16* __restrict__ Blo,
             const float* __restrict__ bias, int Nout,
             __nv_bfloat16* __restrict__ Chi, __nv_bfloat16* __restrict__ Clo,
             float* __restrict__ Zf, __nv_bfloat16* __restrict__ Zhi,
             __nv_bfloat16* __restrict__ Zlo, float* __restrict__ outz)
{
    extern __shared__ char smem[];
    const uint32_t sb = smem_u32(smem);
    const int tid = threadIdx.x;
    const int bx = blockIdx.x, by = blockIdx.y;
    const int lane = tid & 31, warp = tid >> 5;
    const int wm = warp & 1, wn = warp >> 1;
    const int quad = lane >> 3, l8 = lane & 7;

    float* bias_s = (float*)(smem + 131072);
    float* rowsq4 = (float*)(smem + 131072 + 512);   // [4][128]
    if (tid < 128) bias_s[tid] = bias[bx * 128 + tid];

    // loader mapping: 2 threads/row, 4x16B each per tile
    const int lrow = tid >> 1, lhalf = tid & 1;
    const __nv_bfloat16* gA0 = Ahi + (size_t)(by * 128 + lrow) * KK;
    const __nv_bfloat16* gA1 = Alo + (size_t)(by * 128 + lrow) * KK;
    const __nv_bfloat16* gB0 = Bhi + (size_t)(bx * 128 + lrow) * KK;
    const __nv_bfloat16* gB1 = Blo + (size_t)(bx * 128 + lrow) * KK;
    const uint32_t lso = (uint32_t)(lrow >> 3) * 1024 + (lrow & 7) * 16;

    auto load_stage = [&](int kt, int s) {
        uint32_t st = sb + (uint32_t)s * 65536;
        int kbase = kt * 64;
#pragma unroll
        for (int j = 0; j < 4; j++) {
            int kb = lhalf * 4 + j;
            uint32_t so = lso + (uint32_t)kb * 128;
            cp16(st + so,          gA0 + kbase + kb * 8);
            cp16(st + 16384 + so,  gA1 + kbase + kb * 8);
            cp16(st + 32768 + so,  gB0 + kbase + kb * 8);
            cp16(st + 49152 + so,  gB1 + kbase + kb * 8);
        }
        CP_COMMIT();
    };

    float acc[4][4][4];
#pragma unroll
    for (int f = 0; f < 4; f++)
#pragma unroll
        for (int n = 0; n < 4; n++)
#pragma unroll
            for (int q = 0; q < 4; q++) acc[f][n][q] = 0.f;

    const uint32_t aoff = (uint32_t)(quad & 1) * 1024 + (uint32_t)(quad >> 1) * 128 + l8 * 16;
    const uint32_t boff = (uint32_t)(quad >> 1) * 1024 + (uint32_t)(quad & 1) * 128 + l8 * 16;

    load_stage(0, 0);
    for (int kt = 0; kt < KK / 64; kt++) {
        if (kt < KK / 64 - 1) { load_stage(kt + 1, (kt + 1) & 1); CP_WAIT(1); }
        else                  { CP_WAIT(0); }
        __syncthreads();
        const uint32_t st = sb + (uint32_t)(kt & 1) * 65536;
#pragma unroll
        for (int ks = 0; ks < 4; ks++) {
            uint32_t ah[4][4], al[4][4], bh[2][4], bl[2][4];
#pragma unroll
            for (int f = 0; f < 4; f++) {
                uint32_t base = (uint32_t)(wm * 8 + f * 2) * 1024 + ks * 256 + aoff;
                ldsm4(ah[f], st + base);
                ldsm4(al[f], st + 16384 + base);
            }
#pragma unroll
            for (int p = 0; p < 2; p++) {
                uint32_t base = (uint32_t)(wn * 4 + p * 2) * 1024 + ks * 256 + boff;
                ldsm4(bh[p], st + 32768 + base);
                ldsm4(bl[p], st + 49152 + base);
            }
#pragma unroll
            for (int f = 0; f < 4; f++)
#pragma unroll
                for (int nf = 0; nf < 4; nf++) {
                    int p = nf >> 1, q = (nf & 1) * 2;
                    mma_bf16(acc[f][nf], ah[f], bh[p][q], bh[p][q + 1]);
                    mma_bf16(acc[f][nf], al[f], bh[p][q], bh[p][q + 1]);
                    mma_bf16(acc[f][nf], ah[f], bl[p][q], bl[p][q + 1]);
                }
        }
        __syncthreads();
    }

    // ---- epilogue ----
    const int rsub = lane >> 2;            // 0..7
    const int csub = (lane & 3) * 2;       // 0,2,4,6
    if (!NORM) {
#pragma unroll
        for (int f = 0; f < 4; f++) {
            int r0 = by * 128 + wm * 64 + f * 16 + rsub;
#pragma unroll
            for (int nf = 0; nf < 4; nf++) {
                int cn = wn * 32 + nf * 8 + csub;
                float b0 = bias_s[cn], b1 = bias_s[cn + 1];
                float v00 = fmaxf(acc[f][nf][0] + b0, 0.f);
                float v01 = fmaxf(acc[f][nf][1] + b1, 0.f);
                float v10 = fmaxf(acc[f][nf][2] + b0, 0.f);
                float v11 = fmaxf(acc[f][nf][3] + b1, 0.f);
                __nv_bfloat16 h00 = __float2bfloat16_rn(v00);
                __nv_bfloat16 h01 = __float2bfloat16_rn(v01);
                __nv_bfloat16 h10 = __float2bfloat16_rn(v10);
                __nv_bfloat16 h11 = __float2bfloat16_rn(v11);
                size_t o0 = (size_t)r0 * Nout + bx * 128 + cn;
                size_t o1 = o0 + (size_t)8 * Nout;
                *(uint32_t*)(Chi + o0) = pack2bf(v00, v01);
                *(uint32_t*)(Chi + o1) = pack2bf(v10, v11);
                *(uint32_t*)(Clo + o0) = pack2bf(v00 - __bfloat162float(h00),
                                                 v01 - __bfloat162float(h01));
                *(uint32_t*)(Clo + o1) = pack2bf(v10 - __bfloat162float(h10),
                                                 v11 - __bfloat162float(h11));
            }
        }
    } else {
        // per-row sum of squares (deterministic: per-warp slot then sum)
#pragma unroll
        for (int f = 0; f < 4; f++) {
            float s0 = 0.f, s1 = 0.f;
#pragma unroll
            for (int nf = 0; nf < 4; nf++) {
                int cn = wn * 32 + nf * 8 + csub;
                float b0 = bias_s[cn], b1 = bias_s[cn + 1];
                float v00 = acc[f][nf][0] + b0, v01 = acc[f][nf][1] + b1;
                float v10 = acc[f][nf][2] + b0, v11 = acc[f][nf][3] + b1;
                s0 += v00 * v00 + v01 * v01;
                s1 += v10 * v10 + v11 * v11;
            }
            s0 += __shfl_xor_sync(0xffffffffu, s0, 1);
            s0 += __shfl_xor_sync(0xffffffffu, s0, 2);
            s1 += __shfl_xor_sync(0xffffffffu, s1, 1);
            s1 += __shfl_xor_sync(0xffffffffu, s1, 2);
            if ((lane & 3) == 0) {
                int lr = wm * 64 + f * 16 + rsub;
                rowsq4[wn * 128 + lr] = s0;
                rowsq4[wn * 128 + lr + 8] = s1;
            }
        }
        __syncthreads();
#pragma unroll
        for (int f = 0; f < 4; f++) {
            int lr0 = wm * 64 + f * 16 + rsub;
            float sq0 = rowsq4[lr0] + rowsq4[128 + lr0] + rowsq4[256 + lr0] + rowsq4[384 + lr0];
            float sq1 = rowsq4[lr0 + 8] + rowsq4[128 + lr0 + 8] + rowsq4[256 + lr0 + 8] + rowsq4[384 + lr0 + 8];
            float inv0 = rsqrtf(fmaxf(sq0, 1e-24f));
            float inv1 = rsqrtf(fmaxf(sq1, 1e-24f));
            int r0 = by * 128 + lr0;
#pragma unroll
            for (int nf = 0; nf < 4; nf++) {
                int cn = wn * 32 + nf * 8 + csub;
                float b0 = bias_s[cn], b1 = bias_s[cn + 1];
                float z00 = (acc[f][nf][0] + b0) * inv0, z01 = (acc[f][nf][1] + b1) * inv0;
                float z10 = (acc[f][nf][2] + b0) * inv1, z11 = (acc[f][nf][3] + b1) * inv1;
                size_t o0 = (size_t)r0 * FF + cn;
                size_t o1 = o0 + (size_t)8 * FF;
                *(float2*)(Zf + o0) = make_float2(z00, z01);
                *(float2*)(Zf + o1) = make_float2(z10, z11);
                if (outz) {
                    // outz = d_out + 1 is only 4B-aligned: scalar stores only
                    outz[o0]     = z00;
                    outz[o0 + 1] = z01;
                    outz[o1]     = z10;
                    outz[o1 + 1] = z11;
                }
                __nv_bfloat16 h00 = __float2bfloat16_rn(z00);
                __nv_bfloat16 h01 = __float2bfloat16_rn(z01);
                __nv_bfloat16 h10 = __float2bfloat16_rn(z10);
                __nv_bfloat16 h11 = __float2bfloat16_rn(z11);
                *(uint32_t*)(Zhi + o0) = pack2bf(z00, z01);
                *(uint32_t*)(Zhi + o1) = pack2bf(z10, z11);
                *(uint32_t*)(Zlo + o0) = pack2bf(z00 - __bfloat162float(h00),
                                                 z01 - __bfloat162float(h01));
                *(uint32_t*)(Zlo + o1) = pack2bf(z10 - __bfloat162float(h10),
                                                 z11 - __bfloat162float(h11));
            }
        }
    }
}

// ---------------------------------------------------------------------------
// HMMA masked logsumexp: per 128-row block, stream all 128 col tiles.
// A (z rows, hi/lo) resident in smem; B double-buffered; poly exp on FMA pipe.
// ---------------------------------------------------------------------------
__global__ __launch_bounds__(256)
void lse_hmma_k(const __nv_bfloat16* __restrict__ Zhi, const __nv_bfloat16* __restrict__ Zlo,
                float* __restrict__ lse)
{
    extern __shared__ char smem[];
    const uint32_t sb = smem_u32(smem);
    const int tid = threadIdx.x;
    const int by = blockIdx.x;
    const int lane = tid & 31, warp = tid >> 5;
    const int wm = warp & 1, wn = warp >> 1;
    const int quad = lane >> 3, l8 = lane & 7;

    float* lsum4 = (float*)(smem + 196608);  // [4][128]

    const int lrow = tid >> 1, lhalf = tid & 1;
    const uint32_t lso = (uint32_t)(lrow >> 3) * 2048 + (lrow & 7) * 16;

    // load A (z rows of this block), no commit yet
    {
        const __nv_bfloat16* ga0 = Zhi + (size_t)(by * 128 + lrow) * FF;
        const __nv_bfloat16* ga1 = Zlo + (size_t)(by * 128 + lrow) * FF;
#pragma unroll
        for (int j = 0; j < 8; j++) {
            int kb = lhalf * 8 + j;
            cp16(sb + lso + kb * 128,         ga0 + kb * 8);
            cp16(sb + 32768 + lso + kb * 128, ga1 + kb * 8);
        }
    }
    auto loadB = [&](int bxt, int s) {
        uint32_t st = sb + 65536 + (uint32_t)s * 65536;
        const __nv_bfloat16* gb0 = Zhi + (size_t)(bxt * 128 + lrow) * FF;
        const __nv_bfloat16* gb1 = Zlo + (size_t)(bxt * 128 + lrow) * FF;
#pragma unroll
        for (int j = 0; j < 8; j++) {
            int kb = lhalf * 8 + j;
            cp16(st + lso + kb * 128,         gb0 + kb * 8);
            cp16(st + 32768 + lso + kb * 128, gb1 + kb * 8);
        }
        CP_COMMIT();
    };
    loadB(0, 0);   // commits A too

    float rs[4][2];
#pragma unroll
    for (int f = 0; f < 4; f++) { rs[f][0] = 0.f; rs[f][1] = 0.f; }

    const uint32_t aoff = (uint32_t)(quad & 1) * 2048 + (uint32_t)(quad >> 1) * 128 + l8 * 16;
    const uint32_t boff = (uint32_t)(quad >> 1) * 2048 + (uint32_t)(quad & 1) * 128 + l8 * 16;
    const int rsub = lane >> 2;
    const int csub = (lane & 3) * 2;

    for (int bxt = 0; bxt < MB / 128; bxt++) {
        const int s = bxt & 1;
        if (bxt < MB / 128 - 1) { loadB(bxt + 1, s ^ 1); CP_WAIT(1); }
        else                    { CP_WAIT(0); }
        __syncthreads();

        float acc[4][4][4];
#pragma unroll
        for (int f = 0; f < 4; f++)
#pragma unroll
            for (int n = 0; n < 4; n++)
#pragma unroll
                for (int q = 0; q < 4; q++) acc[f][n][q] = 0.f;

        const uint32_t stB = sb + 65536 + (uint32_t)s * 65536;
#pragma unroll
        for (int ks = 0; ks < 8; ks++) {
            uint32_t ah[4][4], al[4][4], bh[2][4], bl[2][4];
#pragma unroll
            for (int f = 0; f < 4; f++) {
                uint32_t base = (uint32_t)(wm * 8 + f * 2) * 2048 + ks * 256 + aoff;
                ldsm4(ah[f], sb + base);
                ldsm4(al[f], sb + 32768 + base);
            }
#pragma unroll
            for (int p = 0; p < 2; p++) {
                uint32_t base = (uint32_t)(wn * 4 + p * 2) * 2048 + ks * 256 + boff;
                ldsm4(bh[p], stB + base);
                ldsm4(bl[p], stB + 32768 + base);
            }
#pragma unroll
            for (int f = 0; f < 4; f++)
#pragma unroll
                for (int nf = 0; nf < 4; nf++) {
                    int p = nf >> 1, q = (nf & 1) * 2;
                    mma_bf16(acc[f][nf], ah[f], bh[p][q], bh[p][q + 1]);
                    mma_bf16(acc[f][nf], al[f], bh[p][q], bh[p][q + 1]);
                    mma_bf16(acc[f][nf], ah[f], bl[p][q], bl[p][q + 1]);
                }
        }
        __syncthreads();   // stage s gets overwritten next iteration

        // exp-sum epilogue (FMA-pipe exp); mask diagonal only on the diag tile
        const bool diag = (bxt == by);
#pragma unroll
        for (int f = 0; f < 4; f++) {
#pragma unroll
            for (int nf = 0; nf < 4; nf++) {
                float e00 = fexp(fmaf(acc[f][nf][0], INV_T, -INV_T));
                float e01 = fexp(fmaf(acc[f][nf][1], INV_T, -INV_T));
                float e10 = fexp(fmaf(acc[f][nf][2], INV_T, -INV_T));
                float e11 = fexp(fmaf(acc[f][nf][3], INV_T, -INV_T));
                if (diag) {
                    int lr = wm * 64 + f * 16 + rsub;
                    int lc = wn * 32 + nf * 8 + csub;
                    if (lr == lc)         e00 = 0.f;
                    if (lr == lc + 1)     e01 = 0.f;
                    if (lr + 8 == lc)     e10 = 0.f;
                    if (lr + 8 == lc + 1) e11 = 0.f;
                }
                rs[f][0] += e00 + e01;
                rs[f][1] += e10 + e11;
            }
        }
    }

    // deterministic reduction: quad -> per-warp slot -> sum of 4
#pragma unroll
    for (int f = 0; f < 4; f++) {
#pragma unroll
        for (int h = 0; h < 2; h++) {
            float v = rs[f][h];
            v += __shfl_xor_sync(0xffffffffu, v, 1);
            v += __shfl_xor_sync(0xffffffffu, v, 2);
            if ((lane & 3) == 0)
                lsum4[wn * 128 + wm * 64 + f * 16 + h * 8 + rsub] = v;
        }
    }
    __syncthreads();
    if (tid < 128) {
        float tot = lsum4[tid] + lsum4[128 + tid] + lsum4[256 + tid] + lsum4[384 + tid];
        lse[by * 128 + tid] = logf(tot) + INV_T;
    }
}

// ---------------------------------------------------------------------------
__global__ void pos_k(const float* __restrict__ Z, float* __restrict__ pos)
{
    const int row = blockIdx.x;
    const int t = threadIdx.x;
    const int prow = (row + MB / 2) & (MB - 1);
    float s = Z[(size_t)row * FF + t] * Z[(size_t)prow * FF + t];
#pragma unroll
    for (int o = 16; o; o >>= 1) s += __shfl_xor_sync(0xffffffffu, s, o);
    __shared__ float ws[4];
    if ((t & 31) == 0) ws[t >> 5] = s;
    __syncthreads();
    if (t == 0) pos[row] = (ws[0] + ws[1] + ws[2] + ws[3]) * INV_T;
}

__global__ void loss_k(const float* __restrict__ lse, const float* __restrict__ pos,
                       float* __restrict__ out)
{
    __shared__ float sm[256];
    const int t = threadIdx.x;
    float s = 0.f;
    for (int i = t; i < MB; i += 256) s += lse[i] - pos[i];
    sm[t] = s;
    __syncthreads();
    for (int o = 128; o; o >>= 1) {
        if (t < o) sm[t] += sm[t + o];
        __syncthreads();
    }
    if (t == 0) out[0] = sm[0] * (1.0f / MB);
}

// ---------------------------------------------------------------------------
extern "C" void kernel_launch(void* const* d_in, const int* in_sizes, int n_in,
                              void* d_out, int out_size)
{
    const float* features = (const float*)d_in[0];
    const float* w1 = (const float*)d_in[1];
    const float* b1 = (const float*)d_in[2];
    const float* w2 = (const float*)d_in[3];
    const float* b2 = (const float*)d_in[4];
    float* out = (float*)d_out;

    __nv_bfloat16 *fhi, *flo, *w1hi, *w1lo, *w2hi, *w2lo, *hhi, *hlo, *zhi, *zlo;
    float *z, *lseb, *posb;
    cudaGetSymbolAddress((void**)&fhi,  g_fhi);
    cudaGetSymbolAddress((void**)&flo,  g_flo);
    cudaGetSymbolAddress((void**)&w1hi, g_w1hi);
    cudaGetSymbolAddress((void**)&w1lo, g_w1lo);
    cudaGetSymbolAddress((void**)&w2hi, g_w2hi);
    cudaGetSymbolAddress((void**)&w2lo, g_w2lo);
    cudaGetSymbolAddress((void**)&hhi,  g_hhi);
    cudaGetSymbolAddress((void**)&hlo,  g_hlo);
    cudaGetSymbolAddress((void**)&zhi,  g_zhi);
    cudaGetSymbolAddress((void**)&zlo,  g_zlo);
    cudaGetSymbolAddress((void**)&z,    g_z);
    cudaGetSymbolAddress((void**)&lseb, g_lse);
    cudaGetSymbolAddress((void**)&posb, g_pos);

    const int SM_G = 131072 + 512 + 2048;   // stages + bias + rowsq4
    const int SM_L = 196608 + 2048;         // A + 2 B stages + lsum4
    cudaFuncSetAttribute(hgemm_k<false>, cudaFuncAttributeMaxDynamicSharedMemorySize, SM_G);
    cudaFuncSetAttribute(hgemm_k<true>,  cudaFuncAttributeMaxDynamicSharedMemorySize, SM_G);
    cudaFuncSetAttribute(lse_hmma_k,     cudaFuncAttributeMaxDynamicSharedMemorySize, SM_L);

    // prep
    split_k<<<2048, 256>>>(features, fhi, flo, (size_t)MB * DD);
    tsplit_k<<<dim3(HH / 32, DD / 32), dim3(32, 8)>>>(w1, w1hi, w1lo, DD, HH);
    tsplit_k<<<dim3(FF / 32, HH / 32), dim3(32, 8)>>>(w2, w2hi, w2lo, HH, FF);

    // 1) h = relu(features @ w1 + b1), emit bf16 hi/lo
    hgemm_k<false><<<dim3(HH / 128, MB / 128), 256, SM_G>>>(
        fhi, flo, w1hi, w1lo, b1, HH, hhi, hlo,
        nullptr, nullptr, nullptr, nullptr);

    // 2) p = h @ w2 + b2, fused L2-normalize; emit z (fp32), zhi/zlo, out z
    float* outz = (out_size >= 1 + MB * FF) ? (out + 1) : nullptr;
    hgemm_k<true><<<dim3(1, MB / 128), 256, SM_G>>>(
        hhi, hlo, w2hi, w2lo, b2, FF, nullptr, nullptr,
        z, zhi, zlo, outz);

    // 3) pos, 4) masked row logsumexp (HMMA + poly exp), 5) loss
    pos_k<<<MB, 128>>>(z, posb);
    lse_hmma_k<<<MB / 128, 256, SM_L>>>(zhi, zlo, lseb);
    loss_k<<<1, 256>>>(lseb, posb, out);
}

// round 5
// speedup vs baseline: 3.3651x; 1.3655x over previous
#include <cuda_runtime.h>
#include <cuda_fp16.h>
#include <math.h>
#include <stdint.h>

#define MB 16384   // rows (2N)
#define DD 2048
#define HH 2048
#define FF 128
#define KK 2048    // K of both big GEMMs

constexpr float INV_T = 1.0f / 0.07f;

// ---------------- scratch --------------------------------------------------
__device__ __half g_fhi [(size_t)MB * DD];
__device__ __half g_flo [(size_t)MB * DD];
__device__ __half g_w1hi[(size_t)HH * DD];
__device__ __half g_w1lo[(size_t)HH * DD];
__device__ __half g_w2hi[(size_t)FF * HH];
__device__ __half g_w2lo[(size_t)FF * HH];
__device__ __half g_hhi [(size_t)MB * HH];
__device__ __half g_hlo [(size_t)MB * HH];
__device__ __half g_zhi [(size_t)MB * FF];
__device__ float g_z  [(size_t)MB * FF];
__device__ float g_ps [2 * MB];     // partial exp-sums (2 column splits)
__device__ float g_pos[MB];

// ---------------- helpers ---------------------------------------------------
__device__ __forceinline__ uint32_t smem_u32(const void* p) {
    uint32_t a;
    asm("{ .reg .u64 t; cvta.to.shared.u64 t, %1; cvt.u32.u64 %0, t; }"
        : "=r"(a) : "l"(p));
    return a;
}
__device__ __forceinline__ void cp16(uint32_t s, const void* g) {
    asm volatile("cp.async.cg.shared.global [%0], [%1], 16;" :: "r"(s), "l"(g));
}
#define CP_COMMIT() asm volatile("cp.async.commit_group;")
#define CP_WAIT(n)  asm volatile("cp.async.wait_group %0;" :: "n"(n))

__device__ __forceinline__ void ldsm4(uint32_t* r, uint32_t a) {
    asm volatile("ldmatrix.sync.aligned.m8n8.x4.shared.b16 {%0,%1,%2,%3}, [%4];"
                 : "=r"(r[0]), "=r"(r[1]), "=r"(r[2]), "=r"(r[3]) : "r"(a));
}
__device__ __forceinline__ void mma_f16(float* c, const uint32_t* a,
                                        uint32_t b0, uint32_t b1) {
    asm volatile(
        "mma.sync.aligned.m16n8k16.row.col.f32.f16.f16.f32 "
        "{%0,%1,%2,%3}, {%4,%5,%6,%7}, {%8,%9}, {%0,%1,%2,%3};"
        : "+f"(c[0]), "+f"(c[1]), "+f"(c[2]), "+f"(c[3])
        : "r"(a[0]), "r"(a[1]), "r"(a[2]), "r"(a[3]), "r"(b0), "r"(b1));
}
__device__ __forceinline__ uint32_t pack2h(float a, float b) {
    __half2 t = __floats2half2_rn(a, b);
    return *reinterpret_cast<uint32_t*>(&t);
}
// fast exp on FMA/ALU pipes (no MUFU): y in [-45, 0.2], abs err ~2e-6
__device__ __forceinline__ float fexp(float y) {
    float t = fmaf(y, 1.4426950408889634f, 12582912.0f);
    int ki = __float_as_int(t) - 0x4B400000;
    float k = t - 12582912.0f;
    float r = fmaf(k, -0.693359375f, y);
    r = fmaf(k, 2.12194440e-4f, r);
    float p = fmaf(r, 8.33333333e-3f, 4.16666667e-2f);
    p = fmaf(p, r, 1.66666667e-1f);
    p = fmaf(p, r, 5.0e-1f);
    p = fmaf(p, r, 1.0f);
    p = fmaf(p, r, 1.0f);
    return __int_as_float(__float_as_int(p) + (ki << 23));
}

// ---------------------------------------------------------------------------
// prep: fp32 -> fp16 (hi, lo) split; and transpose+split for weights
// ---------------------------------------------------------------------------
__global__ void split_k(const float* __restrict__ X, __half* __restrict__ Hi,
                        __half* __restrict__ Lo, size_t n)
{
    size_t stride = (size_t)gridDim.x * blockDim.x * 4;
    for (size_t i = ((size_t)blockIdx.x * blockDim.x + threadIdx.x) * 4; i < n; i += stride) {
        float4 v = *(const float4*)(X + i);
        float vv[4] = {v.x, v.y, v.z, v.w};
        __half h[4], l[4];
#pragma unroll
        for (int k = 0; k < 4; k++) {
            h[k] = __float2half_rn(vv[k]);
            l[k] = __float2half_rn(vv[k] - __half2float(h[k]));
        }
        *(uint2*)(Hi + i) = *(uint2*)h;
        *(uint2*)(Lo + i) = *(uint2*)l;
    }
}
__global__ void tsplit_k(const float* __restrict__ W, __half* __restrict__ Thi,
                         __half* __restrict__ Tlo, int K, int N)
{
    __shared__ float t[32][33];
    int nx = blockIdx.x * 32, ky = blockIdx.y * 32;
    int tx = threadIdx.x, ty = threadIdx.y;   // 32 x 8
#pragma unroll
    for (int i = 0; i < 4; i++)
        t[ty + 8 * i][tx] = W[(size_t)(ky + ty + 8 * i) * N + nx + tx];
    __syncthreads();
#pragma unroll
    for (int i = 0; i < 4; i++) {
        float v = t[tx][ty + 8 * i];
        __half h = __float2half_rn(v);
        __half l = __float2half_rn(v - __half2float(h));
        size_t o = (size_t)(nx + ty + 8 * i) * K + ky + tx;
        Thi[o] = h;
        Tlo[o] = l;
    }
}

// ---------------------------------------------------------------------------
// HMMA split-fp16 GEMM: C = act(A[M,K] @ B^T + bias), B stored [N][K].
// 128x128 block, Kc=32, 3-stage cp.async, 8 warps, 2 CTAs/SM.
// smem/stage = 4 tiles x 8KB = 32KB. Total 96KB + bias + rowsq.
// ---------------------------------------------------------------------------
template<bool NORM>
__global__ __launch_bounds__(256, 2)
void hgemm_k(const __half* __restrict__ Ahi, const __half* __restrict__ Alo,
             const __half* __restrict__ Bhi, const __half* __restrict__ Blo,
             const float* __restrict__ bias, int Nout,
             __half* __restrict__ Chi, __half* __restrict__ Clo,
             float* __restrict__ Zf, __half* __restrict__ Zhi,
             float* __restrict__ outz)
{
    extern __shared__ char smem[];
    const uint32_t sb = smem_u32(smem);
    const int tid = threadIdx.x;
    const int bx = blockIdx.x, by = blockIdx.y;
    const int lane = tid & 31, warp = tid >> 5;
    const int wm = warp & 1, wn = warp >> 1;
    const int quad = lane >> 3, l8 = lane & 7;

    float* bias_s = (float*)(smem + 98304);
    float* rowsq4 = (float*)(smem + 98304 + 512);   // [4][128]
    if (tid < 128) bias_s[tid] = bias[bx * 128 + tid];

    const int lrow = tid >> 1, lhalf = tid & 1;
    const __half* gA0 = Ahi + (size_t)(by * 128 + lrow) * KK;
    const __half* gA1 = Alo + (size_t)(by * 128 + lrow) * KK;
    const __half* gB0 = Bhi + (size_t)(bx * 128 + lrow) * KK;
    const __half* gB1 = Blo + (size_t)(bx * 128 + lrow) * KK;
    const uint32_t lso = (uint32_t)(lrow >> 3) * 512 + (lrow & 7) * 16;

    auto load_stage = [&](int kt, int buf) {
        uint32_t st = sb + (uint32_t)buf * 32768;
        const int kbase = kt * 32;
#pragma unroll
        for (int j = 0; j < 2; j++) {
            int kb = lhalf * 2 + j;
            uint32_t so = lso + (uint32_t)kb * 128;
            cp16(st + so,          gA0 + kbase + kb * 8);
            cp16(st + 8192 + so,   gA1 + kbase + kb * 8);
            cp16(st + 16384 + so,  gB0 + kbase + kb * 8);
            cp16(st + 24576 + so,  gB1 + kbase + kb * 8);
        }
        CP_COMMIT();
    };

    float acc[4][4][4];
#pragma unroll
    for (int f = 0; f < 4; f++)
#pragma unroll
        for (int n = 0; n < 4; n++)
#pragma unroll
            for (int q = 0; q < 4; q++) acc[f][n][q] = 0.f;

    const uint32_t aoff = (uint32_t)(quad & 1) * 512 + (uint32_t)(quad >> 1) * 128 + l8 * 16;
    const uint32_t boff = (uint32_t)(quad >> 1) * 512 + (uint32_t)(quad & 1) * 128 + l8 * 16;

    const int NKT = KK / 32;   // 64
    load_stage(0, 0);
    load_stage(1, 1);
    load_stage(2, 2);
    int buf = 0;
    for (int kt = 0; kt < NKT; kt++) {
        CP_WAIT(2);
        __syncthreads();
        const uint32_t st = sb + (uint32_t)buf * 32768;
#pragma unroll
        for (int ks = 0; ks < 2; ks++) {
            uint32_t ah[4][4], al[4][4], bh[2][4], bl[2][4];
#pragma unroll
            for (int f = 0; f < 4; f++) {
                uint32_t base = (uint32_t)(wm * 8 + f * 2) * 512 + ks * 256 + aoff;
                ldsm4(ah[f], st + base);
                ldsm4(al[f], st + 8192 + base);
            }
#pragma unroll
            for (int p = 0; p < 2; p++) {
                uint32_t base = (uint32_t)(wn * 4 + p * 2) * 512 + ks * 256 + boff;
                ldsm4(bh[p], st + 16384 + base);
                ldsm4(bl[p], st + 24576 + base);
            }
#pragma unroll
            for (int f = 0; f < 4; f++)
#pragma unroll
                for (int nf = 0; nf < 4; nf++) {
                    int p = nf >> 1, q = (nf & 1) * 2;
                    mma_f16(acc[f][nf], ah[f], bh[p][q], bh[p][q + 1]);
                    mma_f16(acc[f][nf], al[f], bh[p][q], bh[p][q + 1]);
                    mma_f16(acc[f][nf], ah[f], bl[p][q], bl[p][q + 1]);
                }
        }
        __syncthreads();
        if (kt + 3 < NKT) load_stage(kt + 3, buf);
        else              CP_COMMIT();
        buf = (buf == 2) ? 0 : buf + 1;
    }

    // ---- epilogue ----
    const int rsub = lane >> 2;
    const int csub = (lane & 3) * 2;
    if (!NORM) {
#pragma unroll
        for (int f = 0; f < 4; f++) {
            int r0 = by * 128 + wm * 64 + f * 16 + rsub;
#pragma unroll
            for (int nf = 0; nf < 4; nf++) {
                int cn = wn * 32 + nf * 8 + csub;
                float b0 = bias_s[cn], b1 = bias_s[cn + 1];
                float v00 = fmaxf(acc[f][nf][0] + b0, 0.f);
                float v01 = fmaxf(acc[f][nf][1] + b1, 0.f);
                float v10 = fmaxf(acc[f][nf][2] + b0, 0.f);
                float v11 = fmaxf(acc[f][nf][3] + b1, 0.f);
                __half h00 = __float2half_rn(v00);
                __half h01 = __float2half_rn(v01);
                __half h10 = __float2half_rn(v10);
                __half h11 = __float2half_rn(v11);
                size_t o0 = (size_t)r0 * Nout + bx * 128 + cn;
                size_t o1 = o0 + (size_t)8 * Nout;
                *(uint32_t*)(Chi + o0) = pack2h(v00, v01);
                *(uint32_t*)(Chi + o1) = pack2h(v10, v11);
                *(uint32_t*)(Clo + o0) = pack2h(v00 - __half2float(h00),
                                                v01 - __half2float(h01));
                *(uint32_t*)(Clo + o1) = pack2h(v10 - __half2float(h10),
                                                v11 - __half2float(h11));
            }
        }
    } else {
#pragma unroll
        for (int f = 0; f < 4; f++) {
            float s0 = 0.f, s1 = 0.f;
#pragma unroll
            for (int nf = 0; nf < 4; nf++) {
                int cn = wn * 32 + nf * 8 + csub;
                float b0 = bias_s[cn], b1 = bias_s[cn + 1];
                float v00 = acc[f][nf][0] + b0, v01 = acc[f][nf][1] + b1;
                float v10 = acc[f][nf][2] + b0, v11 = acc[f][nf][3] + b1;
                s0 += v00 * v00 + v01 * v01;
                s1 += v10 * v10 + v11 * v11;
            }
            s0 += __shfl_xor_sync(0xffffffffu, s0, 1);
            s0 += __shfl_xor_sync(0xffffffffu, s0, 2);
            s1 += __shfl_xor_sync(0xffffffffu, s1, 1);
            s1 += __shfl_xor_sync(0xffffffffu, s1, 2);
            if ((lane & 3) == 0) {
                int lr = wm * 64 + f * 16 + rsub;
                rowsq4[wn * 128 + lr] = s0;
                rowsq4[wn * 128 + lr + 8] = s1;
            }
        }
        __syncthreads();
#pragma unroll
        for (int f = 0; f < 4; f++) {
            int lr0 = wm * 64 + f * 16 + rsub;
            float sq0 = rowsq4[lr0] + rowsq4[128 + lr0] + rowsq4[256 + lr0] + rowsq4[384 + lr0];
            float sq1 = rowsq4[lr0 + 8] + rowsq4[128 + lr0 + 8] + rowsq4[256 + lr0 + 8] + rowsq4[384 + lr0 + 8];
            float inv0 = rsqrtf(fmaxf(sq0, 1e-24f));
            float inv1 = rsqrtf(fmaxf(sq1, 1e-24f));
            int r0 = by * 128 + lr0;
#pragma unroll
            for (int nf = 0; nf < 4; nf++) {
                int cn = wn * 32 + nf * 8 + csub;
                float b0 = bias_s[cn], b1 = bias_s[cn + 1];
                float z00 = (acc[f][nf][0] + b0) * inv0, z01 = (acc[f][nf][1] + b1) * inv0;
                float z10 = (acc[f][nf][2] + b0) * inv1, z11 = (acc[f][nf][3] + b1) * inv1;
                size_t o0 = (size_t)r0 * FF + cn;
                size_t o1 = o0 + (size_t)8 * FF;
                *(float2*)(Zf + o0) = make_float2(z00, z01);
                *(float2*)(Zf + o1) = make_float2(z10, z11);
                if (outz) {   // d_out+1 is only 4B aligned: scalar stores
                    outz[o0] = z00; outz[o0 + 1] = z01;
                    outz[o1] = z10; outz[o1 + 1] = z11;
                }
                *(uint32_t*)(Zhi + o0) = pack2h(z00, z01);
                *(uint32_t*)(Zhi + o1) = pack2h(z10, z11);
            }
        }
    }
}

// ---------------------------------------------------------------------------
// HMMA masked exp-sum: grid (2 col-splits, 128 row-blocks).
// fp16 hi-only sim (error averages out under softmax weights).
// A resident (32KB), B double-buffered (2x32KB). 2 CTAs/SM.
// ---------------------------------------------------------------------------
__global__ __launch_bounds__(256, 2)
void lse_hmma_k(const __half* __restrict__ Zhi, float* __restrict__ ps)
{
    extern __shared__ char smem[];
    const uint32_t sb = smem_u32(smem);
    const int tid = threadIdx.x;
    const int split = blockIdx.x, by = blockIdx.y;
    const int lane = tid & 31, warp = tid >> 5;
    const int wm = warp & 1, wn = warp >> 1;
    const int quad = lane >> 3, l8 = lane & 7;

    float* lsum4 = (float*)(smem + 98304);   // [4][128]

    const int lrow = tid >> 1, lhalf = tid & 1;
    const uint32_t lso = (uint32_t)(lrow >> 3) * 2048 + (lrow & 7) * 16;

    // A tile (rows of this block): 32KB, 8 cp16/thread
    {
        const __half* ga = Zhi + (size_t)(by * 128 + lrow) * FF;
#pragma unroll
        for (int j = 0; j < 8; j++) {
            int kb = lhalf * 8 + j;
            cp16(sb + lso + kb * 128, ga + kb * 8);
        }
    }
    auto loadB = [&](int bxt, int s) {
        uint32_t st = sb + 32768 + (uint32_t)s * 32768;
        const __half* gb = Zhi + (size_t)(bxt * 128 + lrow) * FF;
#pragma unroll
        for (int j = 0; j < 8; j++) {
            int kb = lhalf * 8 + j;
            cp16(st + lso + kb * 128, gb + kb * 8);
        }
        CP_COMMIT();
    };
    const int bx0 = split * 64;
    loadB(bx0, 0);   // commits A too

    float rs[4][2];
#pragma unroll
    for (int f = 0; f < 4; f++) { rs[f][0] = 0.f; rs[f][1] = 0.f; }

    const uint32_t aoff = (uint32_t)(quad & 1) * 2048 + (uint32_t)(quad >> 1) * 128 + l8 * 16;
    const uint32_t boff = (uint32_t)(quad >> 1) * 2048 + (uint32_t)(quad & 1) * 128 + l8 * 16;
    const int rsub = lane >> 2;
    const int csub = (lane & 3) * 2;

    for (int i = 0; i < 64; i++) {
        const int bxt = bx0 + i;
        const int s = i & 1;
        if (i < 63) { loadB(bx0 + i + 1, s ^ 1); CP_WAIT(1); }
        else        { CP_WAIT(0); }
        __syncthreads();

        float acc[4][4][4];
#pragma unroll
        for (int f = 0; f < 4; f++)
#pragma unroll
            for (int n = 0; n < 4; n++)
#pragma unroll
                for (int q = 0; q < 4; q++) acc[f][n][q] = 0.f;

        const uint32_t stB = sb + 32768 + (uint32_t)s * 32768;
#pragma unroll
        for (int ks = 0; ks < 8; ks++) {
            uint32_t ah[4][4], bh[2][4];
#pragma unroll
            for (int f = 0; f < 4; f++)
                ldsm4(ah[f], sb + (uint32_t)(wm * 8 + f * 2) * 2048 + ks * 256 + aoff);
#pragma unroll
            for (int p = 0; p < 2; p++)
                ldsm4(bh[p], stB + (uint32_t)(wn * 4 + p * 2) * 2048 + ks * 256 + boff);
#pragma unroll
            for (int f = 0; f < 4; f++)
#pragma unroll
                for (int nf = 0; nf < 4; nf++) {
                    int p = nf >> 1, q = (nf & 1) * 2;
                    mma_f16(acc[f][nf], ah[f], bh[p][q], bh[p][q + 1]);
                }
        }
        __syncthreads();

        const bool diag = (bxt == by);
#pragma unroll
        for (int f = 0; f < 4; f++) {
#pragma unroll
            for (int nf = 0; nf < 4; nf++) {
                float e00 = fexp(fmaf(acc[f][nf][0], INV_T, -INV_T));
                float e01 = fexp(fmaf(acc[f][nf][1], INV_T, -INV_T));
                float e10 = fexp(fmaf(acc[f][nf][2], INV_T, -INV_T));
                float e11 = fexp(fmaf(acc[f][nf][3], INV_T, -INV_T));
                if (diag) {
                    int lr = wm * 64 + f * 16 + rsub;
                    int lc = wn * 32 + nf * 8 + csub;
                    if (lr == lc)         e00 = 0.f;
                    if (lr == lc + 1)     e01 = 0.f;
                    if (lr + 8 == lc)     e10 = 0.f;
                    if (lr + 8 == lc + 1) e11 = 0.f;
                }
                rs[f][0] += e00 + e01;
                rs[f][1] += e10 + e11;
            }
        }
    }

#pragma unroll
    for (int f = 0; f < 4; f++) {
#pragma unroll
        for (int h = 0; h < 2; h++) {
            float v = rs[f][h];
            v += __shfl_xor_sync(0xffffffffu, v, 1);
            v += __shfl_xor_sync(0xffffffffu, v, 2);
            if ((lane & 3) == 0)
                lsum4[wn * 128 + wm * 64 + f * 16 + h * 8 + rsub] = v;
        }
    }
    __syncthreads();
    if (tid < 128) {
        float tot = lsum4[tid] + lsum4[128 + tid] + lsum4[256 + tid] + lsum4[384 + tid];
        ps[(size_t)split * MB + by * 128 + tid] = tot;
    }
}

// ---------------------------------------------------------------------------
__global__ void pos_k(const float* __restrict__ Z, float* __restrict__ pos)
{
    const int row = blockIdx.x;
    const int t = threadIdx.x;
    const int prow = (row + MB / 2) & (MB - 1);
    float s = Z[(size_t)row * FF + t] * Z[(size_t)prow * FF + t];
#pragma unroll
    for (int o = 16; o; o >>= 1) s += __shfl_xor_sync(0xffffffffu, s, o);
    __shared__ float ws[4];
    if ((t & 31) == 0) ws[t >> 5] = s;
    __syncthreads();
    if (t == 0) pos[row] = (ws[0] + ws[1] + ws[2] + ws[3]) * INV_T;
}

__global__ void loss_k(const float* __restrict__ ps, const float* __restrict__ pos,
                       float* __restrict__ out)
{
    __shared__ float sm[256];
    const int t = threadIdx.x;
    float s = 0.f;
    for (int i = t; i < MB; i += 256) {
        float tot = ps[i] + ps[MB + i];
        s += logf(tot) + INV_T - pos[i];
    }
    sm[t] = s;
    __syncthreads();
    for (int o = 128; o; o >>= 1) {
        if (t < o) sm[t] += sm[t + o];
        __syncthreads();
    }
    if (t == 0) out[0] = sm[0] * (1.0f / MB);
}

// ---------------------------------------------------------------------------
extern "C" void kernel_launch(void* const* d_in, const int* in_sizes, int n_in,
                              void* d_out, int out_size)
{
    const float* features = (const float*)d_in[0];
    const float* w1 = (const float*)d_in[1];
    const float* b1 = (const float*)d_in[2];
    const float* w2 = (const float*)d_in[3];
    const float* b2 = (const float*)d_in[4];
    float* out = (float*)d_out;

    __half *fhi, *flo, *w1hi, *w1lo, *w2hi, *w2lo, *hhi, *hlo, *zhi;
    float *z, *psb, *posb;
    cudaGetSymbolAddress((void**)&fhi,  g_fhi);
    cudaGetSymbolAddress((void**)&flo,  g_flo);
    cudaGetSymbolAddress((void**)&w1hi, g_w1hi);
    cudaGetSymbolAddress((void**)&w1lo, g_w1lo);
    cudaGetSymbolAddress((void**)&w2hi, g_w2hi);
    cudaGetSymbolAddress((void**)&w2lo, g_w2lo);
    cudaGetSymbolAddress((void**)&hhi,  g_hhi);
    cudaGetSymbolAddress((void**)&hlo,  g_hlo);
    cudaGetSymbolAddress((void**)&zhi,  g_zhi);
    cudaGetSymbolAddress((void**)&z,    g_z);
    cudaGetSymbolAddress((void**)&psb,  g_ps);
    cudaGetSymbolAddress((void**)&posb, g_pos);

    const int SM_G = 98304 + 512 + 2048;   // 3 stages + bias + rowsq
    const int SM_L = 98304 + 2048;         // A + 2 B stages + lsum
    cudaFuncSetAttribute(hgemm_k<false>, cudaFuncAttributeMaxDynamicSharedMemorySize, SM_G);
    cudaFuncSetAttribute(hgemm_k<true>,  cudaFuncAttributeMaxDynamicSharedMemorySize, SM_G);
    cudaFuncSetAttribute(lse_hmma_k,     cudaFuncAttributeMaxDynamicSharedMemorySize, SM_L);

    // prep
    split_k<<<2048, 256>>>(features, fhi, flo, (size_t)MB * DD);
    tsplit_k<<<dim3(HH / 32, DD / 32), dim3(32, 8)>>>(w1, w1hi, w1lo, DD, HH);
    tsplit_k<<<dim3(FF / 32, HH / 32), dim3(32, 8)>>>(w2, w2hi, w2lo, HH, FF);

    // 1) h = relu(features @ w1 + b1), emit fp16 hi/lo
    hgemm_k<false><<<dim3(HH / 128, MB / 128), 256, SM_G>>>(
        fhi, flo, w1hi, w1lo, b1, HH, hhi, hlo, nullptr, nullptr, nullptr);

    // 2) p = h @ w2 + b2, fused L2-normalize; emit z (fp32), zhi, out z
    float* outz = (out_size >= 1 + MB * FF) ? (out + 1) : nullptr;
    hgemm_k<true><<<dim3(1, MB / 128), 256, SM_G>>>(
        hhi, hlo, w2hi, w2lo, b2, FF, nullptr, nullptr, z, zhi, outz);

    // 3) pos, 4) masked exp-sums (2 column splits), 5) loss
    pos_k<<<MB, 128>>>(z, posb);
    lse_hmma_k<<<dim3(2, MB / 128), 256, SM_L>>>(zhi, psb);
    loss_k<<<1, 256>>>(psb, posb, out);
}

// round 6
// speedup vs baseline: 4.0909x; 1.2157x over previous
#include <cuda_runtime.h>
#include <cuda_fp16.h>
#include <math.h>
#include <stdint.h>

#define MB 16384   // rows (2N)
#define DD 2048
#define HH 2048
#define FF 128
#define KK 2048    // K of both big GEMMs

constexpr float INV_T = 1.0f / 0.07f;

// ---------------- scratch --------------------------------------------------
__device__ __half g_fhi [(size_t)MB * DD];
__device__ __half g_flo [(size_t)MB * DD];
__device__ __half g_w1hi[(size_t)HH * DD];
__device__ __half g_w2hi[(size_t)FF * HH];
__device__ __half g_w2lo[(size_t)FF * HH];
__device__ __half g_hhi [(size_t)MB * HH];
__device__ __half g_hlo [(size_t)MB * HH];
__device__ __half g_zhi [(size_t)MB * FF];
__device__ float g_z  [(size_t)MB * FF];
__device__ float g_ps [2 * MB];     // partial exp-sums (2 column splits)
__device__ float g_pos[MB];

// ---------------- helpers ---------------------------------------------------
__device__ __forceinline__ uint32_t smem_u32(const void* p) {
    uint32_t a;
    asm("{ .reg .u64 t; cvta.to.shared.u64 t, %1; cvt.u32.u64 %0, t; }"
        : "=r"(a) : "l"(p));
    return a;
}
__device__ __forceinline__ void cp16(uint32_t s, const void* g) {
    asm volatile("cp.async.cg.shared.global [%0], [%1], 16;" :: "r"(s), "l"(g));
}
#define CP_COMMIT() asm volatile("cp.async.commit_group;")
#define CP_WAIT(n)  asm volatile("cp.async.wait_group %0;" :: "n"(n))

__device__ __forceinline__ void ldsm4(uint32_t* r, uint32_t a) {
    asm volatile("ldmatrix.sync.aligned.m8n8.x4.shared.b16 {%0,%1,%2,%3}, [%4];"
                 : "=r"(r[0]), "=r"(r[1]), "=r"(r[2]), "=r"(r[3]) : "r"(a));
}
__device__ __forceinline__ void mma_f16(float* c, const uint32_t* a,
                                        uint32_t b0, uint32_t b1) {
    asm volatile(
        "mma.sync.aligned.m16n8k16.row.col.f32.f16.f16.f32 "
        "{%0,%1,%2,%3}, {%4,%5,%6,%7}, {%8,%9}, {%0,%1,%2,%3};"
        : "+f"(c[0]), "+f"(c[1]), "+f"(c[2]), "+f"(c[3])
        : "r"(a[0]), "r"(a[1]), "r"(a[2]), "r"(a[3]), "r"(b0), "r"(b1));
}
__device__ __forceinline__ uint32_t pack2h(float a, float b) {
    __half2 t = __floats2half2_rn(a, b);
    return *reinterpret_cast<uint32_t*>(&t);
}
// fast exp on FMA/ALU pipes (no MUFU): y in [-45, 0.2], abs err ~2e-6
__device__ __forceinline__ float fexp(float y) {
    float t = fmaf(y, 1.4426950408889634f, 12582912.0f);
    int ki = __float_as_int(t) - 0x4B400000;
    float k = t - 12582912.0f;
    float r = fmaf(k, -0.693359375f, y);
    r = fmaf(k, 2.12194440e-4f, r);
    float p = fmaf(r, 8.33333333e-3f, 4.16666667e-2f);
    p = fmaf(p, r, 1.66666667e-1f);
    p = fmaf(p, r, 5.0e-1f);
    p = fmaf(p, r, 1.0f);
    p = fmaf(p, r, 1.0f);
    return __int_as_float(__float_as_int(p) + (ki << 23));
}

// ---------------------------------------------------------------------------
// prep kernels
// ---------------------------------------------------------------------------
__global__ void split_k(const float* __restrict__ X, __half* __restrict__ Hi,
                        __half* __restrict__ Lo, size_t n)
{
    size_t stride = (size_t)gridDim.x * blockDim.x * 4;
    for (size_t i = ((size_t)blockIdx.x * blockDim.x + threadIdx.x) * 4; i < n; i += stride) {
        float4 v = *(const float4*)(X + i);
        float vv[4] = {v.x, v.y, v.z, v.w};
        __half h[4], l[4];
#pragma unroll
        for (int k = 0; k < 4; k++) {
            h[k] = __float2half_rn(vv[k]);
            l[k] = __float2half_rn(vv[k] - __half2float(h[k]));
        }
        *(uint2*)(Hi + i) = *(uint2*)h;
        *(uint2*)(Lo + i) = *(uint2*)l;
    }
}
// transpose; lo output optional
__global__ void tsplit_k(const float* __restrict__ W, __half* __restrict__ Thi,
                         __half* __restrict__ Tlo, int K, int N)
{
    __shared__ float t[32][33];
    int nx = blockIdx.x * 32, ky = blockIdx.y * 32;
    int tx = threadIdx.x, ty = threadIdx.y;   // 32 x 8
#pragma unroll
    for (int i = 0; i < 4; i++)
        t[ty + 8 * i][tx] = W[(size_t)(ky + ty + 8 * i) * N + nx + tx];
    __syncthreads();
#pragma unroll
    for (int i = 0; i < 4; i++) {
        float v = t[tx][ty + 8 * i];
        __half h = __float2half_rn(v);
        size_t o = (size_t)(nx + ty + 8 * i) * K + ky + tx;
        Thi[o] = h;
        if (Tlo) Tlo[o] = __float2half_rn(v - __half2float(h));
    }
}

// ---------------------------------------------------------------------------
// GEMM1: 2-term split (a_hi*b_hi + a_lo*b_hi), B_lo never loaded.
// C = relu(A @ B^T + bias). 128x128 block, Kc=64, 2-stage, 2 CTAs/SM.
// stage = 3 tiles x 16KB = 48KB.
// ---------------------------------------------------------------------------
__global__ __launch_bounds__(256, 2)
void hgemm1_k(const __half* __restrict__ Ahi, const __half* __restrict__ Alo,
              const __half* __restrict__ Bhi, const float* __restrict__ bias,
              int Nout, __half* __restrict__ Chi, __half* __restrict__ Clo)
{
    extern __shared__ char smem[];
    const uint32_t sb = smem_u32(smem);
    const int tid = threadIdx.x;
    const int bx = blockIdx.x, by = blockIdx.y;
    const int lane = tid & 31, warp = tid >> 5;
    const int wm = warp & 1, wn = warp >> 1;
    const int quad = lane >> 3, l8 = lane & 7;

    float* bias_s = (float*)(smem + 98304);
    if (tid < 128) bias_s[tid] = bias[bx * 128 + tid];

    const int lrow = tid >> 1, lhalf = tid & 1;
    const __half* gA0 = Ahi + (size_t)(by * 128 + lrow) * KK;
    const __half* gA1 = Alo + (size_t)(by * 128 + lrow) * KK;
    const __half* gB0 = Bhi + (size_t)(bx * 128 + lrow) * KK;
    const uint32_t lso = (uint32_t)(lrow >> 3) * 1024 + (lrow & 7) * 16;

    auto load_stage = [&](int kt, int s) {
        uint32_t st = sb + (uint32_t)s * 49152;
        const int kbase = kt * 64;
#pragma unroll
        for (int j = 0; j < 4; j++) {
            int kb = lhalf * 4 + j;
            uint32_t so = lso + (uint32_t)kb * 128;
            cp16(st + so,          gA0 + kbase + kb * 8);
            cp16(st + 16384 + so,  gA1 + kbase + kb * 8);
            cp16(st + 32768 + so,  gB0 + kbase + kb * 8);
        }
        CP_COMMIT();
    };

    float acc[4][4][4];
#pragma unroll
    for (int f = 0; f < 4; f++)
#pragma unroll
        for (int n = 0; n < 4; n++)
#pragma unroll
            for (int q = 0; q < 4; q++) acc[f][n][q] = 0.f;

    const uint32_t aoff = (uint32_t)(quad & 1) * 1024 + (uint32_t)(quad >> 1) * 128 + l8 * 16;
    const uint32_t boff = (uint32_t)(quad >> 1) * 1024 + (uint32_t)(quad & 1) * 128 + l8 * 16;

    const int NKT = KK / 64;   // 32
    load_stage(0, 0);
    for (int kt = 0; kt < NKT; kt++) {
        if (kt < NKT - 1) { load_stage(kt + 1, (kt + 1) & 1); CP_WAIT(1); }
        else              { CP_WAIT(0); }
        __syncthreads();
        const uint32_t st = sb + (uint32_t)(kt & 1) * 49152;
#pragma unroll
        for (int ks = 0; ks < 4; ks++) {
            uint32_t ah[4][4], al[4][4], bh[2][4];
#pragma unroll
            for (int f = 0; f < 4; f++) {
                uint32_t base = (uint32_t)(wm * 8 + f * 2) * 1024 + ks * 256 + aoff;
                ldsm4(ah[f], st + base);
                ldsm4(al[f], st + 16384 + base);
            }
#pragma unroll
            for (int p = 0; p < 2; p++)
                ldsm4(bh[p], st + 32768 + (uint32_t)(wn * 4 + p * 2) * 1024 + ks * 256 + boff);
#pragma unroll
            for (int f = 0; f < 4; f++)
#pragma unroll
                for (int nf = 0; nf < 4; nf++) {
                    int p = nf >> 1, q = (nf & 1) * 2;
                    mma_f16(acc[f][nf], ah[f], bh[p][q], bh[p][q + 1]);
                    mma_f16(acc[f][nf], al[f], bh[p][q], bh[p][q + 1]);
                }
        }
        __syncthreads();
    }

    const int rsub = lane >> 2;
    const int csub = (lane & 3) * 2;
#pragma unroll
    for (int f = 0; f < 4; f++) {
        int r0 = by * 128 + wm * 64 + f * 16 + rsub;
#pragma unroll
        for (int nf = 0; nf < 4; nf++) {
            int cn = wn * 32 + nf * 8 + csub;
            float b0 = bias_s[cn], b1 = bias_s[cn + 1];
            float v00 = fmaxf(acc[f][nf][0] + b0, 0.f);
            float v01 = fmaxf(acc[f][nf][1] + b1, 0.f);
            float v10 = fmaxf(acc[f][nf][2] + b0, 0.f);
            float v11 = fmaxf(acc[f][nf][3] + b1, 0.f);
            __half h00 = __float2half_rn(v00);
            __half h01 = __float2half_rn(v01);
            __half h10 = __float2half_rn(v10);
            __half h11 = __float2half_rn(v11);
            size_t o0 = (size_t)r0 * Nout + bx * 128 + cn;
            size_t o1 = o0 + (size_t)8 * Nout;
            *(uint32_t*)(Chi + o0) = pack2h(v00, v01);
            *(uint32_t*)(Chi + o1) = pack2h(v10, v11);
            *(uint32_t*)(Clo + o0) = pack2h(v00 - __half2float(h00),
                                            v01 - __half2float(h01));
            *(uint32_t*)(Clo + o1) = pack2h(v10 - __half2float(h10),
                                            v11 - __half2float(h11));
        }
    }
}

// ---------------------------------------------------------------------------
// GEMM2 (3-term split) + fused L2-normalize. Kc=32, 3-stage, 2 CTAs/SM.
// ---------------------------------------------------------------------------
__global__ __launch_bounds__(256, 2)
void hgemm2_k(const __half* __restrict__ Ahi, const __half* __restrict__ Alo,
              const __half* __restrict__ Bhi, const __half* __restrict__ Blo,
              const float* __restrict__ bias,
              float* __restrict__ Zf, __half* __restrict__ Zhi,
              float* __restrict__ outz)
{
    extern __shared__ char smem[];
    const uint32_t sb = smem_u32(smem);
    const int tid = threadIdx.x;
    const int bx = blockIdx.x, by = blockIdx.y;
    const int lane = tid & 31, warp = tid >> 5;
    const int wm = warp & 1, wn = warp >> 1;
    const int quad = lane >> 3, l8 = lane & 7;

    float* bias_s = (float*)(smem + 98304);
    float* rowsq4 = (float*)(smem + 98304 + 512);
    if (tid < 128) bias_s[tid] = bias[bx * 128 + tid];

    const int lrow = tid >> 1, lhalf = tid & 1;
    const __half* gA0 = Ahi + (size_t)(by * 128 + lrow) * KK;
    const __half* gA1 = Alo + (size_t)(by * 128 + lrow) * KK;
    const __half* gB0 = Bhi + (size_t)(bx * 128 + lrow) * KK;
    const __half* gB1 = Blo + (size_t)(bx * 128 + lrow) * KK;
    const uint32_t lso = (uint32_t)(lrow >> 3) * 512 + (lrow & 7) * 16;

    auto load_stage = [&](int kt, int buf) {
        uint32_t st = sb + (uint32_t)buf * 32768;
        const int kbase = kt * 32;
#pragma unroll
        for (int j = 0; j < 2; j++) {
            int kb = lhalf * 2 + j;
            uint32_t so = lso + (uint32_t)kb * 128;
            cp16(st + so,          gA0 + kbase + kb * 8);
            cp16(st + 8192 + so,   gA1 + kbase + kb * 8);
            cp16(st + 16384 + so,  gB0 + kbase + kb * 8);
            cp16(st + 24576 + so,  gB1 + kbase + kb * 8);
        }
        CP_COMMIT();
    };

    float acc[4][4][4];
#pragma unroll
    for (int f = 0; f < 4; f++)
#pragma unroll
        for (int n = 0; n < 4; n++)
#pragma unroll
            for (int q = 0; q < 4; q++) acc[f][n][q] = 0.f;

    const uint32_t aoff = (uint32_t)(quad & 1) * 512 + (uint32_t)(quad >> 1) * 128 + l8 * 16;
    const uint32_t boff = (uint32_t)(quad >> 1) * 512 + (uint32_t)(quad & 1) * 128 + l8 * 16;

    const int NKT = KK / 32;
    load_stage(0, 0);
    load_stage(1, 1);
    load_stage(2, 2);
    int buf = 0;
    for (int kt = 0; kt < NKT; kt++) {
        CP_WAIT(2);
        __syncthreads();
        const uint32_t st = sb + (uint32_t)buf * 32768;
#pragma unroll
        for (int ks = 0; ks < 2; ks++) {
            uint32_t ah[4][4], al[4][4], bh[2][4], bl[2][4];
#pragma unroll
            for (int f = 0; f < 4; f++) {
                uint32_t base = (uint32_t)(wm * 8 + f * 2) * 512 + ks * 256 + aoff;
                ldsm4(ah[f], st + base);
                ldsm4(al[f], st + 8192 + base);
            }
#pragma unroll
            for (int p = 0; p < 2; p++) {
                uint32_t base = (uint32_t)(wn * 4 + p * 2) * 512 + ks * 256 + boff;
                ldsm4(bh[p], st + 16384 + base);
                ldsm4(bl[p], st + 24576 + base);
            }
#pragma unroll
            for (int f = 0; f < 4; f++)
#pragma unroll
                for (int nf = 0; nf < 4; nf++) {
                    int p = nf >> 1, q = (nf & 1) * 2;
                    mma_f16(acc[f][nf], ah[f], bh[p][q], bh[p][q + 1]);
                    mma_f16(acc[f][nf], al[f], bh[p][q], bh[p][q + 1]);
                    mma_f16(acc[f][nf], ah[f], bl[p][q], bl[p][q + 1]);
                }
        }
        __syncthreads();
        if (kt + 3 < NKT) load_stage(kt + 3, buf);
        else              CP_COMMIT();
        buf = (buf == 2) ? 0 : buf + 1;
    }

    const int rsub = lane >> 2;
    const int csub = (lane & 3) * 2;
#pragma unroll
    for (int f = 0; f < 4; f++) {
        float s0 = 0.f, s1 = 0.f;
#pragma unroll
        for (int nf = 0; nf < 4; nf++) {
            int cn = wn * 32 + nf * 8 + csub;
            float b0 = bias_s[cn], b1 = bias_s[cn + 1];
            float v00 = acc[f][nf][0] + b0, v01 = acc[f][nf][1] + b1;
            float v10 = acc[f][nf][2] + b0, v11 = acc[f][nf][3] + b1;
            s0 += v00 * v00 + v01 * v01;
            s1 += v10 * v10 + v11 * v11;
        }
        s0 += __shfl_xor_sync(0xffffffffu, s0, 1);
        s0 += __shfl_xor_sync(0xffffffffu, s0, 2);
        s1 += __shfl_xor_sync(0xffffffffu, s1, 1);
        s1 += __shfl_xor_sync(0xffffffffu, s1, 2);
        if ((lane & 3) == 0) {
            int lr = wm * 64 + f * 16 + rsub;
            rowsq4[wn * 128 + lr] = s0;
            rowsq4[wn * 128 + lr + 8] = s1;
        }
    }
    __syncthreads();
#pragma unroll
    for (int f = 0; f < 4; f++) {
        int lr0 = wm * 64 + f * 16 + rsub;
        float sq0 = rowsq4[lr0] + rowsq4[128 + lr0] + rowsq4[256 + lr0] + rowsq4[384 + lr0];
        float sq1 = rowsq4[lr0 + 8] + rowsq4[128 + lr0 + 8] + rowsq4[256 + lr0 + 8] + rowsq4[384 + lr0 + 8];
        float inv0 = rsqrtf(fmaxf(sq0, 1e-24f));
        float inv1 = rsqrtf(fmaxf(sq1, 1e-24f));
        int r0 = by * 128 + lr0;
#pragma unroll
        for (int nf = 0; nf < 4; nf++) {
            int cn = wn * 32 + nf * 8 + csub;
            float b0 = bias_s[cn], b1 = bias_s[cn + 1];
            float z00 = (acc[f][nf][0] + b0) * inv0, z01 = (acc[f][nf][1] + b1) * inv0;
            float z10 = (acc[f][nf][2] + b0) * inv1, z11 = (acc[f][nf][3] + b1) * inv1;
            size_t o0 = (size_t)r0 * FF + cn;
            size_t o1 = o0 + (size_t)8 * FF;
            *(float2*)(Zf + o0) = make_float2(z00, z01);
            *(float2*)(Zf + o1) = make_float2(z10, z11);
            if (outz) {   // d_out+1 only 4B aligned: scalar stores
                outz[o0] = z00; outz[o0 + 1] = z01;
                outz[o1] = z10; outz[o1 + 1] = z11;
            }
            *(uint32_t*)(Zhi + o0) = pack2h(z00, z01);
            *(uint32_t*)(Zhi + o1) = pack2h(z10, z11);
        }
    }
}

// ---------------------------------------------------------------------------
// HMMA masked exp-sum: grid (2 col-splits, 128 row-blocks), fp16 hi-only sim.
// ---------------------------------------------------------------------------
__global__ __launch_bounds__(256, 2)
void lse_hmma_k(const __half* __restrict__ Zhi, float* __restrict__ ps)
{
    extern __shared__ char smem[];
    const uint32_t sb = smem_u32(smem);
    const int tid = threadIdx.x;
    const int split = blockIdx.x, by = blockIdx.y;
    const int lane = tid & 31, warp = tid >> 5;
    const int wm = warp & 1, wn = warp >> 1;
    const int quad = lane >> 3, l8 = lane & 7;

    float* lsum4 = (float*)(smem + 98304);

    const int lrow = tid >> 1, lhalf = tid & 1;
    const uint32_t lso = (uint32_t)(lrow >> 3) * 2048 + (lrow & 7) * 16;

    {
        const __half* ga = Zhi + (size_t)(by * 128 + lrow) * FF;
#pragma unroll
        for (int j = 0; j < 8; j++) {
            int kb = lhalf * 8 + j;
            cp16(sb + lso + kb * 128, ga + kb * 8);
        }
    }
    auto loadB = [&](int bxt, int s) {
        uint32_t st = sb + 32768 + (uint32_t)s * 32768;
        const __half* gb = Zhi + (size_t)(bxt * 128 + lrow) * FF;
#pragma unroll
        for (int j = 0; j < 8; j++) {
            int kb = lhalf * 8 + j;
            cp16(st + lso + kb * 128, gb + kb * 8);
        }
        CP_COMMIT();
    };
    const int bx0 = split * 64;
    loadB(bx0, 0);

    float rs[4][2];
#pragma unroll
    for (int f = 0; f < 4; f++) { rs[f][0] = 0.f; rs[f][1] = 0.f; }

    const uint32_t aoff = (uint32_t)(quad & 1) * 2048 + (uint32_t)(quad >> 1) * 128 + l8 * 16;
    const uint32_t boff = (uint32_t)(quad >> 1) * 2048 + (uint32_t)(quad & 1) * 128 + l8 * 16;
    const int rsub = lane >> 2;
    const int csub = (lane & 3) * 2;

    for (int i = 0; i < 64; i++) {
        const int bxt = bx0 + i;
        const int s = i & 1;
        if (i < 63) { loadB(bx0 + i + 1, s ^ 1); CP_WAIT(1); }
        else        { CP_WAIT(0); }
        __syncthreads();

        float acc[4][4][4];
#pragma unroll
        for (int f = 0; f < 4; f++)
#pragma unroll
            for (int n = 0; n < 4; n++)
#pragma unroll
                for (int q = 0; q < 4; q++) acc[f][n][q] = 0.f;

        const uint32_t stB = sb + 32768 + (uint32_t)s * 32768;
#pragma unroll
        for (int ks = 0; ks < 8; ks++) {
            uint32_t ah[4][4], bh[2][4];
#pragma unroll
            for (int f = 0; f < 4; f++)
                ldsm4(ah[f], sb + (uint32_t)(wm * 8 + f * 2) * 2048 + ks * 256 + aoff);
#pragma unroll
            for (int p = 0; p < 2; p++)
                ldsm4(bh[p], stB + (uint32_t)(wn * 4 + p * 2) * 2048 + ks * 256 + boff);
#pragma unroll
            for (int f = 0; f < 4; f++)
#pragma unroll
                for (int nf = 0; nf < 4; nf++) {
                    int p = nf >> 1, q = (nf & 1) * 2;
                    mma_f16(acc[f][nf], ah[f], bh[p][q], bh[p][q + 1]);
                }
        }
        __syncthreads();

        const bool diag = (bxt == by);
#pragma unroll
        for (int f = 0; f < 4; f++) {
#pragma unroll
            for (int nf = 0; nf < 4; nf++) {
                float e00 = fexp(fmaf(acc[f][nf][0], INV_T, -INV_T));
                float e01 = fexp(fmaf(acc[f][nf][1], INV_T, -INV_T));
                float e10 = fexp(fmaf(acc[f][nf][2], INV_T, -INV_T));
                float e11 = fexp(fmaf(acc[f][nf][3], INV_T, -INV_T));
                if (diag) {
                    int lr = wm * 64 + f * 16 + rsub;
                    int lc = wn * 32 + nf * 8 + csub;
                    if (lr == lc)         e00 = 0.f;
                    if (lr == lc + 1)     e01 = 0.f;
                    if (lr + 8 == lc)     e10 = 0.f;
                    if (lr + 8 == lc + 1) e11 = 0.f;
                }
                rs[f][0] += e00 + e01;
                rs[f][1] += e10 + e11;
            }
        }
    }

#pragma unroll
    for (int f = 0; f < 4; f++) {
#pragma unroll
        for (int h = 0; h < 2; h++) {
            float v = rs[f][h];
            v += __shfl_xor_sync(0xffffffffu, v, 1);
            v += __shfl_xor_sync(0xffffffffu, v, 2);
            if ((lane & 3) == 0)
                lsum4[wn * 128 + wm * 64 + f * 16 + h * 8 + rsub] = v;
        }
    }
    __syncthreads();
    if (tid < 128) {
        float tot = lsum4[tid] + lsum4[128 + tid] + lsum4[256 + tid] + lsum4[384 + tid];
        ps[(size_t)split * MB + by * 128 + tid] = tot;
    }
}

// ---------------------------------------------------------------------------
__global__ void pos_k(const float* __restrict__ Z, float* __restrict__ pos)
{
    const int row = blockIdx.x;
    const int t = threadIdx.x;
    const int prow = (row + MB / 2) & (MB - 1);
    float s = Z[(size_t)row * FF + t] * Z[(size_t)prow * FF + t];
#pragma unroll
    for (int o = 16; o; o >>= 1) s += __shfl_xor_sync(0xffffffffu, s, o);
    __shared__ float ws[4];
    if ((t & 31) == 0) ws[t >> 5] = s;
    __syncthreads();
    if (t == 0) pos[row] = (ws[0] + ws[1] + ws[2] + ws[3]) * INV_T;
}

__global__ void loss_k(const float* __restrict__ ps, const float* __restrict__ pos,
                       float* __restrict__ out)
{
    __shared__ float sm[256];
    const int t = threadIdx.x;
    float s = 0.f;
    for (int i = t; i < MB; i += 256) {
        float tot = ps[i] + ps[MB + i];
        s += logf(tot) + INV_T - pos[i];
    }
    sm[t] = s;
    __syncthreads();
    for (int o = 128; o; o >>= 1) {
        if (t < o) sm[t] += sm[t + o];
        __syncthreads();
    }
    if (t == 0) out[0] = sm[0] * (1.0f / MB);
}

// ---------------------------------------------------------------------------
extern "C" void kernel_launch(void* const* d_in, const int* in_sizes, int n_in,
                              void* d_out, int out_size)
{
    const float* features = (const float*)d_in[0];
    const float* w1 = (const float*)d_in[1];
    const float* b1 = (const float*)d_in[2];
    const float* w2 = (const float*)d_in[3];
    const float* b2 = (const float*)d_in[4];
    float* out = (float*)d_out;

    __half *fhi, *flo, *w1hi, *w2hi, *w2lo, *hhi, *hlo, *zhi;
    float *z, *psb, *posb;
    cudaGetSymbolAddress((void**)&fhi,  g_fhi);
    cudaGetSymbolAddress((void**)&flo,  g_flo);
    cudaGetSymbolAddress((void**)&w1hi, g_w1hi);
    cudaGetSymbolAddress((void**)&w2hi, g_w2hi);
    cudaGetSymbolAddress((void**)&w2lo, g_w2lo);
    cudaGetSymbolAddress((void**)&hhi,  g_hhi);
    cudaGetSymbolAddress((void**)&hlo,  g_hlo);
    cudaGetSymbolAddress((void**)&zhi,  g_zhi);
    cudaGetSymbolAddress((void**)&z,    g_z);
    cudaGetSymbolAddress((void**)&psb,  g_ps);
    cudaGetSymbolAddress((void**)&posb, g_pos);

    const int SM_G1 = 98304 + 512;          // 2 stages x 48KB + bias
    const int SM_G2 = 98304 + 512 + 2048;   // 3 stages x 32KB + bias + rowsq
    const int SM_L  = 98304 + 2048;         // A + 2 B stages + lsum
    cudaFuncSetAttribute(hgemm1_k,  cudaFuncAttributeMaxDynamicSharedMemorySize, SM_G1);
    cudaFuncSetAttribute(hgemm2_k,  cudaFuncAttributeMaxDynamicSharedMemorySize, SM_G2);
    cudaFuncSetAttribute(lse_hmma_k, cudaFuncAttributeMaxDynamicSharedMemorySize, SM_L);

    // prep (w1 lo never needed — 2-term GEMM1)
    split_k<<<2048, 256>>>(features, fhi, flo, (size_t)MB * DD);
    tsplit_k<<<dim3(HH / 32, DD / 32), dim3(32, 8)>>>(w1, w1hi, nullptr, DD, HH);
    tsplit_k<<<dim3(FF / 32, HH / 32), dim3(32, 8)>>>(w2, w2hi, w2lo, HH, FF);

    // 1) h = relu(features @ w1 + b1), 2-term split
    hgemm1_k<<<dim3(HH / 128, MB / 128), 256, SM_G1>>>(
        fhi, flo, w1hi, b1, HH, hhi, hlo);

    // 2) p = h @ w2 + b2 (3-term), fused L2-normalize
    float* outz = (out_size >= 1 + MB * FF) ? (out + 1) : nullptr;
    hgemm2_k<<<dim3(1, MB / 128), 256, SM_G2>>>(
        hhi, hlo, w2hi, w2lo, b2, z, zhi, outz);

    // 3) pos, 4) masked exp-sums, 5) loss
    pos_k<<<MB, 128>>>(z, posb);
    lse_hmma_k<<<dim3(2, MB / 128), 256, SM_L>>>(zhi, psb);
    loss_k<<<1, 256>>>(psb, posb, out);
}

// round 7
// speedup vs baseline: 4.4736x; 1.0935x over previous
#include <cuda_runtime.h>
#include <cuda_fp16.h>
#include <math.h>
#include <stdint.h>

#define MB 16384   // rows (2N)
#define DD 2048
#define HH 2048
#define FF 128
#define KK 2048    // K of both big GEMMs

constexpr float INV_T = 1.0f / 0.07f;

// ---------------- scratch --------------------------------------------------
__device__ __half g_fhi [(size_t)MB * DD];
__device__ __half g_flo [(size_t)MB * DD];
__device__ __half g_w1hi[(size_t)HH * DD];
__device__ __half g_w2hi[(size_t)FF * HH];
__device__ __half g_w2lo[(size_t)FF * HH];
__device__ __half g_hhi [(size_t)MB * HH];
__device__ __half g_hlo [(size_t)MB * HH];
__device__ __half g_zhi [(size_t)MB * FF];
__device__ float g_z  [(size_t)MB * FF];
__device__ float g_ps [2 * MB];     // partial exp-sums (2 column splits)
__device__ float g_pos[MB];

// ---------------- helpers ---------------------------------------------------
__device__ __forceinline__ uint32_t smem_u32(const void* p) {
    uint32_t a;
    asm("{ .reg .u64 t; cvta.to.shared.u64 t, %1; cvt.u32.u64 %0, t; }"
        : "=r"(a) : "l"(p));
    return a;
}
__device__ __forceinline__ void cp16(uint32_t s, const void* g) {
    asm volatile("cp.async.cg.shared.global [%0], [%1], 16;" :: "r"(s), "l"(g));
}
#define CP_COMMIT() asm volatile("cp.async.commit_group;")
#define CP_WAIT(n)  asm volatile("cp.async.wait_group %0;" :: "n"(n))

__device__ __forceinline__ void ldsm4(uint32_t* r, uint32_t a) {
    asm volatile("ldmatrix.sync.aligned.m8n8.x4.shared.b16 {%0,%1,%2,%3}, [%4];"
                 : "=r"(r[0]), "=r"(r[1]), "=r"(r[2]), "=r"(r[3]) : "r"(a));
}
__device__ __forceinline__ void mma_f16(float* c, const uint32_t* a,
                                        uint32_t b0, uint32_t b1) {
    asm volatile(
        "mma.sync.aligned.m16n8k16.row.col.f32.f16.f16.f32 "
        "{%0,%1,%2,%3}, {%4,%5,%6,%7}, {%8,%9}, {%0,%1,%2,%3};"
        : "+f"(c[0]), "+f"(c[1]), "+f"(c[2]), "+f"(c[3])
        : "r"(a[0]), "r"(a[1]), "r"(a[2]), "r"(a[3]), "r"(b0), "r"(b1));
}
__device__ __forceinline__ uint32_t pack2h(float a, float b) {
    __half2 t = __floats2half2_rn(a, b);
    return *reinterpret_cast<uint32_t*>(&t);
}
// fast exp on FMA/ALU pipes: y in [-45, 0.2], abs err ~1e-6
__device__ __forceinline__ float fexp(float y) {
    float t = fmaf(y, 1.4426950408889634f, 12582912.0f);
    int ki = __float_as_int(t) - 0x4B400000;
    float k = t - 12582912.0f;
    float r = fmaf(k, -0.69314718055994531f, y);
    float p = fmaf(r, 8.33333333e-3f, 4.16666667e-2f);
    p = fmaf(p, r, 1.66666667e-1f);
    p = fmaf(p, r, 5.0e-1f);
    p = fmaf(p, r, 1.0f);
    p = fmaf(p, r, 1.0f);
    return __int_as_float(__float_as_int(p) + (ki << 23));
}

// ---------------------------------------------------------------------------
// prep kernels
// ---------------------------------------------------------------------------
__global__ void split_k(const float* __restrict__ X, __half* __restrict__ Hi,
                        __half* __restrict__ Lo, size_t n)
{
    size_t stride = (size_t)gridDim.x * blockDim.x * 4;
    for (size_t i = ((size_t)blockIdx.x * blockDim.x + threadIdx.x) * 4; i < n; i += stride) {
        float4 v = *(const float4*)(X + i);
        float vv[4] = {v.x, v.y, v.z, v.w};
        __half h[4], l[4];
#pragma unroll
        for (int k = 0; k < 4; k++) {
            h[k] = __float2half_rn(vv[k]);
            l[k] = __float2half_rn(vv[k] - __half2float(h[k]));
        }
        *(uint2*)(Hi + i) = *(uint2*)h;
        *(uint2*)(Lo + i) = *(uint2*)l;
    }
}
__global__ void tsplit_k(const float* __restrict__ W, __half* __restrict__ Thi,
                         __half* __restrict__ Tlo, int K, int N)
{
    __shared__ float t[32][33];
    int nx = blockIdx.x * 32, ky = blockIdx.y * 32;
    int tx = threadIdx.x, ty = threadIdx.y;   // 32 x 8
#pragma unroll
    for (int i = 0; i < 4; i++)
        t[ty + 8 * i][tx] = W[(size_t)(ky + ty + 8 * i) * N + nx + tx];
    __syncthreads();
#pragma unroll
    for (int i = 0; i < 4; i++) {
        float v = t[tx][ty + 8 * i];
        __half h = __float2half_rn(v);
        size_t o = (size_t)(nx + ty + 8 * i) * K + ky + tx;
        Thi[o] = h;
        if (Tlo) Tlo[o] = __float2half_rn(v - __half2float(h));
    }
}

// ---------------------------------------------------------------------------
// GEMM1: 2-term split (a_hi*b_hi + a_lo*b_hi), B_lo never loaded.
// 128x128 block, Kc=32, 4-stage cp.async pipeline, ONE sync per iteration.
// stage = 3 tiles x 8KB = 24KB; 4 stages = 96KB; 2 CTAs/SM.
// ---------------------------------------------------------------------------
__global__ __launch_bounds__(256, 2)
void hgemm1_k(const __half* __restrict__ Ahi, const __half* __restrict__ Alo,
              const __half* __restrict__ Bhi, const float* __restrict__ bias,
              int Nout, __half* __restrict__ Chi, __half* __restrict__ Clo)
{
    extern __shared__ char smem[];
    const uint32_t sb = smem_u32(smem);
    const int tid = threadIdx.x;
    const int bx = blockIdx.x, by = blockIdx.y;
    const int lane = tid & 31, warp = tid >> 5;
    const int wm = warp & 1, wn = warp >> 1;
    const int quad = lane >> 3, l8 = lane & 7;

    float* bias_s = (float*)(smem + 98304);
    if (tid < 128) bias_s[tid] = bias[bx * 128 + tid];

    const int lrow = tid >> 1, lhalf = tid & 1;
    const __half* gA0 = Ahi + (size_t)(by * 128 + lrow) * KK;
    const __half* gA1 = Alo + (size_t)(by * 128 + lrow) * KK;
    const __half* gB0 = Bhi + (size_t)(bx * 128 + lrow) * KK;
    const uint32_t lso = (uint32_t)(lrow >> 3) * 512 + (lrow & 7) * 16;

    auto load_stage = [&](int kt) {
        uint32_t st = sb + (uint32_t)(kt & 3) * 24576;
        const int kbase = kt * 32;
#pragma unroll
        for (int j = 0; j < 2; j++) {
            int kb = lhalf * 2 + j;
            uint32_t so = lso + (uint32_t)kb * 128;
            cp16(st + so,          gA0 + kbase + kb * 8);
            cp16(st + 8192 + so,   gA1 + kbase + kb * 8);
            cp16(st + 16384 + so,  gB0 + kbase + kb * 8);
        }
        CP_COMMIT();
    };

    float acc[4][4][4];
#pragma unroll
    for (int f = 0; f < 4; f++)
#pragma unroll
        for (int n = 0; n < 4; n++)
#pragma unroll
            for (int q = 0; q < 4; q++) acc[f][n][q] = 0.f;

    const uint32_t aoff = (uint32_t)(quad & 1) * 512 + (uint32_t)(quad >> 1) * 128 + l8 * 16;
    const uint32_t boff = (uint32_t)(quad >> 1) * 512 + (uint32_t)(quad & 1) * 128 + l8 * 16;

    const int NKT = KK / 32;   // 64
    load_stage(0);
    load_stage(1);
    load_stage(2);
    for (int kt = 0; kt < NKT; kt++) {
        CP_WAIT(2);
        __syncthreads();
        // stage (kt+3)%4 == (kt-1)%4 was consumed at kt-1; sync above makes
        // overwrite safe, and issuing now gives the load 3 chunks to land.
        if (kt + 3 < NKT) load_stage(kt + 3);
        const uint32_t st = sb + (uint32_t)(kt & 3) * 24576;
#pragma unroll
        for (int ks = 0; ks < 2; ks++) {
            uint32_t ah[4][4], al[4][4], bh[2][4];
#pragma unroll
            for (int f = 0; f < 4; f++) {
                uint32_t base = (uint32_t)(wm * 8 + f * 2) * 512 + ks * 256 + aoff;
                ldsm4(ah[f], st + base);
                ldsm4(al[f], st + 8192 + base);
            }
#pragma unroll
            for (int p = 0; p < 2; p++)
                ldsm4(bh[p], st + 16384 + (uint32_t)(wn * 4 + p * 2) * 512 + ks * 256 + boff);
#pragma unroll
            for (int f = 0; f < 4; f++)
#pragma unroll
                for (int nf = 0; nf < 4; nf++) {
                    int p = nf >> 1, q = (nf & 1) * 2;
                    mma_f16(acc[f][nf], ah[f], bh[p][q], bh[p][q + 1]);
                    mma_f16(acc[f][nf], al[f], bh[p][q], bh[p][q + 1]);
                }
        }
    }

    const int rsub = lane >> 2;
    const int csub = (lane & 3) * 2;
#pragma unroll
    for (int f = 0; f < 4; f++) {
        int r0 = by * 128 + wm * 64 + f * 16 + rsub;
#pragma unroll
        for (int nf = 0; nf < 4; nf++) {
            int cn = wn * 32 + nf * 8 + csub;
            float b0 = bias_s[cn], b1 = bias_s[cn + 1];
            float v00 = fmaxf(acc[f][nf][0] + b0, 0.f);
            float v01 = fmaxf(acc[f][nf][1] + b1, 0.f);
            float v10 = fmaxf(acc[f][nf][2] + b0, 0.f);
            float v11 = fmaxf(acc[f][nf][3] + b1, 0.f);
            __half h00 = __float2half_rn(v00);
            __half h01 = __float2half_rn(v01);
            __half h10 = __float2half_rn(v10);
            __half h11 = __float2half_rn(v11);
            size_t o0 = (size_t)r0 * Nout + bx * 128 + cn;
            size_t o1 = o0 + (size_t)8 * Nout;
            *(uint32_t*)(Chi + o0) = pack2h(v00, v01);
            *(uint32_t*)(Chi + o1) = pack2h(v10, v11);
            *(uint32_t*)(Clo + o0) = pack2h(v00 - __half2float(h00),
                                            v01 - __half2float(h01));
            *(uint32_t*)(Clo + o1) = pack2h(v10 - __half2float(h10),
                                            v11 - __half2float(h11));
        }
    }
}

// ---------------------------------------------------------------------------
// GEMM2 (3-term split) + fused L2-normalize. Kc=32, 3-stage, 2 CTAs/SM.
// ---------------------------------------------------------------------------
__global__ __launch_bounds__(256, 2)
void hgemm2_k(const __half* __restrict__ Ahi, const __half* __restrict__ Alo,
              const __half* __restrict__ Bhi, const __half* __restrict__ Blo,
              const float* __restrict__ bias,
              float* __restrict__ Zf, __half* __restrict__ Zhi,
              float* __restrict__ outz)
{
    extern __shared__ char smem[];
    const uint32_t sb = smem_u32(smem);
    const int tid = threadIdx.x;
    const int bx = blockIdx.x, by = blockIdx.y;
    const int lane = tid & 31, warp = tid >> 5;
    const int wm = warp & 1, wn = warp >> 1;
    const int quad = lane >> 3, l8 = lane & 7;

    float* bias_s = (float*)(smem + 98304);
    float* rowsq4 = (float*)(smem + 98304 + 512);
    if (tid < 128) bias_s[tid] = bias[bx * 128 + tid];

    const int lrow = tid >> 1, lhalf = tid & 1;
    const __half* gA0 = Ahi + (size_t)(by * 128 + lrow) * KK;
    const __half* gA1 = Alo + (size_t)(by * 128 + lrow) * KK;
    const __half* gB0 = Bhi + (size_t)(bx * 128 + lrow) * KK;
    const __half* gB1 = Blo + (size_t)(bx * 128 + lrow) * KK;
    const uint32_t lso = (uint32_t)(lrow >> 3) * 512 + (lrow & 7) * 16;

    auto load_stage = [&](int kt, int buf) {
        uint32_t st = sb + (uint32_t)buf * 32768;
        const int kbase = kt * 32;
#pragma unroll
        for (int j = 0; j < 2; j++) {
            int kb = lhalf * 2 + j;
            uint32_t so = lso + (uint32_t)kb * 128;
            cp16(st + so,          gA0 + kbase + kb * 8);
            cp16(st + 8192 + so,   gA1 + kbase + kb * 8);
            cp16(st + 16384 + so,  gB0 + kbase + kb * 8);
            cp16(st + 24576 + so,  gB1 + kbase + kb * 8);
        }
        CP_COMMIT();
    };

    float acc[4][4][4];
#pragma unroll
    for (int f = 0; f < 4; f++)
#pragma unroll
        for (int n = 0; n < 4; n++)
#pragma unroll
            for (int q = 0; q < 4; q++) acc[f][n][q] = 0.f;

    const uint32_t aoff = (uint32_t)(quad & 1) * 512 + (uint32_t)(quad >> 1) * 128 + l8 * 16;
    const uint32_t boff = (uint32_t)(quad >> 1) * 512 + (uint32_t)(quad & 1) * 128 + l8 * 16;

    const int NKT = KK / 32;
    load_stage(0, 0);
    load_stage(1, 1);
    int buf = 0;
    for (int kt = 0; kt < NKT; kt++) {
        CP_WAIT(1);
        __syncthreads();
        if (kt + 2 < NKT) load_stage(kt + 2, (buf + 2) % 3);
        const uint32_t st = sb + (uint32_t)buf * 32768;
#pragma unroll
        for (int ks = 0; ks < 2; ks++) {
            uint32_t ah[4][4], al[4][4], bh[2][4], bl[2][4];
#pragma unroll
            for (int f = 0; f < 4; f++) {
                uint32_t base = (uint32_t)(wm * 8 + f * 2) * 512 + ks * 256 + aoff;
                ldsm4(ah[f], st + base);
                ldsm4(al[f], st + 8192 + base);
            }
#pragma unroll
            for (int p = 0; p < 2; p++) {
                uint32_t base = (uint32_t)(wn * 4 + p * 2) * 512 + ks * 256 + boff;
                ldsm4(bh[p], st + 16384 + base);
                ldsm4(bl[p], st + 24576 + base);
            }
#pragma unroll
            for (int f = 0; f < 4; f++)
#pragma unroll
                for (int nf = 0; nf < 4; nf++) {
                    int p = nf >> 1, q = (nf & 1) * 2;
                    mma_f16(acc[f][nf], ah[f], bh[p][q], bh[p][q + 1]);
                    mma_f16(acc[f][nf], al[f], bh[p][q], bh[p][q + 1]);
                    mma_f16(acc[f][nf], ah[f], bl[p][q], bl[p][q + 1]);
                }
        }
        buf = (buf + 1) % 3;
    }

    const int rsub = lane >> 2;
    const int csub = (lane & 3) * 2;
#pragma unroll
    for (int f = 0; f < 4; f++) {
        float s0 = 0.f, s1 = 0.f;
#pragma unroll
        for (int nf = 0; nf < 4; nf++) {
            int cn = wn * 32 + nf * 8 + csub;
            float b0 = bias_s[cn], b1 = bias_s[cn + 1];
            float v00 = acc[f][nf][0] + b0, v01 = acc[f][nf][1] + b1;
            float v10 = acc[f][nf][2] + b0, v11 = acc[f][nf][3] + b1;
            s0 += v00 * v00 + v01 * v01;
            s1 += v10 * v10 + v11 * v11;
        }
        s0 += __shfl_xor_sync(0xffffffffu, s0, 1);
        s0 += __shfl_xor_sync(0xffffffffu, s0, 2);
        s1 += __shfl_xor_sync(0xffffffffu, s1, 1);
        s1 += __shfl_xor_sync(0xffffffffu, s1, 2);
        if ((lane & 3) == 0) {
            int lr = wm * 64 + f * 16 + rsub;
            rowsq4[wn * 128 + lr] = s0;
            rowsq4[wn * 128 + lr + 8] = s1;
        }
    }
    __syncthreads();
#pragma unroll
    for (int f = 0; f < 4; f++) {
        int lr0 = wm * 64 + f * 16 + rsub;
        float sq0 = rowsq4[lr0] + rowsq4[128 + lr0] + rowsq4[256 + lr0] + rowsq4[384 + lr0];
        float sq1 = rowsq4[lr0 + 8] + rowsq4[128 + lr0 + 8] + rowsq4[256 + lr0 + 8] + rowsq4[384 + lr0 + 8];
        float inv0 = rsqrtf(fmaxf(sq0, 1e-24f));
        float inv1 = rsqrtf(fmaxf(sq1, 1e-24f));
        int r0 = by * 128 + lr0;
#pragma unroll
        for (int nf = 0; nf < 4; nf++) {
            int cn = wn * 32 + nf * 8 + csub;
            float b0 = bias_s[cn], b1 = bias_s[cn + 1];
            float z00 = (acc[f][nf][0] + b0) * inv0, z01 = (acc[f][nf][1] + b1) * inv0;
            float z10 = (acc[f][nf][2] + b0) * inv1, z11 = (acc[f][nf][3] + b1) * inv1;
            size_t o0 = (size_t)r0 * FF + cn;
            size_t o1 = o0 + (size_t)8 * FF;
            *(float2*)(Zf + o0) = make_float2(z00, z01);
            *(float2*)(Zf + o1) = make_float2(z10, z11);
            if (outz) {   // d_out+1 only 4B aligned: scalar stores
                outz[o0] = z00; outz[o0 + 1] = z01;
                outz[o1] = z10; outz[o1 + 1] = z11;
            }
            *(uint32_t*)(Zhi + o0) = pack2h(z00, z01);
            *(uint32_t*)(Zhi + o1) = pack2h(z10, z11);
        }
    }
}

// ---------------------------------------------------------------------------
// HMMA masked exp-sum: grid (2 col-splits, 128 row-blocks), fp16 hi-only sim.
// ONE sync per tile; B load for i+1 issued right after the sync so it
// overlaps the whole MMA+exp epilogue of tile i.
// ---------------------------------------------------------------------------
__global__ __launch_bounds__(256, 2)
void lse_hmma_k(const __half* __restrict__ Zhi, float* __restrict__ ps)
{
    extern __shared__ char smem[];
    const uint32_t sb = smem_u32(smem);
    const int tid = threadIdx.x;
    const int split = blockIdx.x, by = blockIdx.y;
    const int lane = tid & 31, warp = tid >> 5;
    const int wm = warp & 1, wn = warp >> 1;
    const int quad = lane >> 3, l8 = lane & 7;

    float* lsum4 = (float*)(smem + 98304);

    const int lrow = tid >> 1, lhalf = tid & 1;
    const uint32_t lso = (uint32_t)(lrow >> 3) * 2048 + (lrow & 7) * 16;

    {
        const __half* ga = Zhi + (size_t)(by * 128 + lrow) * FF;
#pragma unroll
        for (int j = 0; j < 8; j++) {
            int kb = lhalf * 8 + j;
            cp16(sb + lso + kb * 128, ga + kb * 8);
        }
    }
    auto loadB = [&](int bxt, int s) {
        uint32_t st = sb + 32768 + (uint32_t)s * 32768;
        const __half* gb = Zhi + (size_t)(bxt * 128 + lrow) * FF;
#pragma unroll
        for (int j = 0; j < 8; j++) {
            int kb = lhalf * 8 + j;
            cp16(st + lso + kb * 128, gb + kb * 8);
        }
        CP_COMMIT();
    };
    const int bx0 = split * 64;
    loadB(bx0, 0);   // commits A too

    float rs[4][2];
#pragma unroll
    for (int f = 0; f < 4; f++) { rs[f][0] = 0.f; rs[f][1] = 0.f; }

    const uint32_t aoff = (uint32_t)(quad & 1) * 2048 + (uint32_t)(quad >> 1) * 128 + l8 * 16;
    const uint32_t boff = (uint32_t)(quad >> 1) * 2048 + (uint32_t)(quad & 1) * 128 + l8 * 16;
    const int rsub = lane >> 2;
    const int csub = (lane & 3) * 2;

    for (int i = 0; i < 64; i++) {
        const int bxt = bx0 + i;
        const int s = i & 1;
        CP_WAIT(0);
        __syncthreads();
        // stage s^1 was consumed at i-1; safe to refill now, overlaps MMA+epi
        if (i < 63) loadB(bx0 + i + 1, s ^ 1);

        float acc[4][4][4];
#pragma unroll
        for (int f = 0; f < 4; f++)
#pragma unroll
            for (int n = 0; n < 4; n++)
#pragma unroll
                for (int q = 0; q < 4; q++) acc[f][n][q] = 0.f;

        const uint32_t stB = sb + 32768 + (uint32_t)s * 32768;
#pragma unroll
        for (int ks = 0; ks < 8; ks++) {
            uint32_t ah[4][4], bh[2][4];
#pragma unroll
            for (int f = 0; f < 4; f++)
                ldsm4(ah[f], sb + (uint32_t)(wm * 8 + f * 2) * 2048 + ks * 256 + aoff);
#pragma unroll
            for (int p = 0; p < 2; p++)
                ldsm4(bh[p], stB + (uint32_t)(wn * 4 + p * 2) * 2048 + ks * 256 + boff);
#pragma unroll
            for (int f = 0; f < 4; f++)
#pragma unroll
                for (int nf = 0; nf < 4; nf++) {
                    int p = nf >> 1, q = (nf & 1) * 2;
                    mma_f16(acc[f][nf], ah[f], bh[p][q], bh[p][q + 1]);
                }
        }

        const bool diag = (bxt == by);
#pragma unroll
        for (int f = 0; f < 4; f++) {
#pragma unroll
            for (int nf = 0; nf < 4; nf++) {
                float e00 = fexp(fmaf(acc[f][nf][0], INV_T, -INV_T));
                float e01 = fexp(fmaf(acc[f][nf][1], INV_T, -INV_T));
                float e10 = fexp(fmaf(acc[f][nf][2], INV_T, -INV_T));
                float e11 = fexp(fmaf(acc[f][nf][3], INV_T, -INV_T));
                if (diag) {
                    int lr = wm * 64 + f * 16 + rsub;
                    int lc = wn * 32 + nf * 8 + csub;
                    if (lr == lc)         e00 = 0.f;
                    if (lr == lc + 1)     e01 = 0.f;
                    if (lr + 8 == lc)     e10 = 0.f;
                    if (lr + 8 == lc + 1) e11 = 0.f;
                }
                rs[f][0] += e00 + e01;
                rs[f][1] += e10 + e11;
            }
        }
    }

#pragma unroll
    for (int f = 0; f < 4; f++) {
#pragma unroll
        for (int h = 0; h < 2; h++) {
            float v = rs[f][h];
            v += __shfl_xor_sync(0xffffffffu, v, 1);
            v += __shfl_xor_sync(0xffffffffu, v, 2);
            if ((lane & 3) == 0)
                lsum4[wn * 128 + wm * 64 + f * 16 + h * 8 + rsub] = v;
        }
    }
    __syncthreads();
    if (tid < 128) {
        float tot = lsum4[tid] + lsum4[128 + tid] + lsum4[256 + tid] + lsum4[384 + tid];
        ps[(size_t)split * MB + by * 128 + tid] = tot;
    }
}

// ---------------------------------------------------------------------------
__global__ void pos_k(const float* __restrict__ Z, float* __restrict__ pos)
{
    const int row = blockIdx.x;
    const int t = threadIdx.x;
    const int prow = (row + MB / 2) & (MB - 1);
    float s = Z[(size_t)row * FF + t] * Z[(size_t)prow * FF + t];
#pragma unroll
    for (int o = 16; o; o >>= 1) s += __shfl_xor_sync(0xffffffffu, s, o);
    __shared__ float ws[4];
    if ((t & 31) == 0) ws[t >> 5] = s;
    __syncthreads();
    if (t == 0) pos[row] = (ws[0] + ws[1] + ws[2] + ws[3]) * INV_T;
}

__global__ void loss_k(const float* __restrict__ ps, const float* __restrict__ pos,
                       float* __restrict__ out)
{
    __shared__ float sm[256];
    const int t = threadIdx.x;
    float s = 0.f;
    for (int i = t; i < MB; i += 256) {
        float tot = ps[i] + ps[MB + i];
        s += logf(tot) + INV_T - pos[i];
    }
    sm[t] = s;
    __syncthreads();
    for (int o = 128; o; o >>= 1) {
        if (t < o) sm[t] += sm[t + o];
        __syncthreads();
    }
    if (t == 0) out[0] = sm[0] * (1.0f / MB);
}

// ---------------------------------------------------------------------------
extern "C" void kernel_launch(void* const* d_in, const int* in_sizes, int n_in,
                              void* d_out, int out_size)
{
    const float* features = (const float*)d_in[0];
    const float* w1 = (const float*)d_in[1];
    const float* b1 = (const float*)d_in[2];
    const float* w2 = (const float*)d_in[3];
    const float* b2 = (const float*)d_in[4];
    float* out = (float*)d_out;

    __half *fhi, *flo, *w1hi, *w2hi, *w2lo, *hhi, *hlo, *zhi;
    float *z, *psb, *posb;
    cudaGetSymbolAddress((void**)&fhi,  g_fhi);
    cudaGetSymbolAddress((void**)&flo,  g_flo);
    cudaGetSymbolAddress((void**)&w1hi, g_w1hi);
    cudaGetSymbolAddress((void**)&w2hi, g_w2hi);
    cudaGetSymbolAddress((void**)&w2lo, g_w2lo);
    cudaGetSymbolAddress((void**)&hhi,  g_hhi);
    cudaGetSymbolAddress((void**)&hlo,  g_hlo);
    cudaGetSymbolAddress((void**)&zhi,  g_zhi);
    cudaGetSymbolAddress((void**)&z,    g_z);
    cudaGetSymbolAddress((void**)&psb,  g_ps);
    cudaGetSymbolAddress((void**)&posb, g_pos);

    const int SM_G1 = 98304 + 512;          // 4 stages x 24KB + bias
    const int SM_G2 = 98304 + 512 + 2048;   // 3 stages x 32KB + bias + rowsq
    const int SM_L  = 98304 + 2048;         // A + 2 B stages + lsum
    cudaFuncSetAttribute(hgemm1_k,  cudaFuncAttributeMaxDynamicSharedMemorySize, SM_G1);
    cudaFuncSetAttribute(hgemm2_k,  cudaFuncAttributeMaxDynamicSharedMemorySize, SM_G2);
    cudaFuncSetAttribute(lse_hmma_k, cudaFuncAttributeMaxDynamicSharedMemorySize, SM_L);

    // prep
    split_k<<<2048, 256>>>(features, fhi, flo, (size_t)MB * DD);
    tsplit_k<<<dim3(HH / 32, DD / 32), dim3(32, 8)>>>(w1, w1hi, nullptr, DD, HH);
    tsplit_k<<<dim3(FF / 32, HH / 32), dim3(32, 8)>>>(w2, w2hi, w2lo, HH, FF);

    // 1) h = relu(features @ w1 + b1), 2-term split
    hgemm1_k<<<dim3(HH / 128, MB / 128), 256, SM_G1>>>(
        fhi, flo, w1hi, b1, HH, hhi, hlo);

    // 2) p = h @ w2 + b2 (3-term), fused L2-normalize
    float* outz = (out_size >= 1 + MB * FF) ? (out + 1) : nullptr;
    hgemm2_k<<<dim3(1, MB / 128), 256, SM_G2>>>(
        hhi, hlo, w2hi, w2lo, b2, z, zhi, outz);

    // 3) pos, 4) masked exp-sums, 5) loss
    pos_k<<<MB, 128>>>(z, posb);
    lse_hmma_k<<<dim3(2, MB / 128), 256, SM_L>>>(zhi, psb);
    loss_k<<<1, 256>>>(psb, posb, out);
}

// round 8
// speedup vs baseline: 6.2471x; 1.3964x over previous
#include <cuda_runtime.h>
#include <cuda_fp16.h>
#include <math.h>
#include <stdint.h>

#define MB 16384   // rows (2N)
#define DD 2048
#define HH 2048
#define FF 128
#define KK 2048    // K of both big GEMMs

constexpr float INV_T = 1.0f / 0.07f;

// ---------------- scratch --------------------------------------------------
__device__ __half g_fhi [(size_t)MB * DD];
__device__ __half g_w1hi[(size_t)HH * DD];
__device__ __half g_w2hi[(size_t)FF * HH];
__device__ __half g_w2lo[(size_t)FF * HH];
__device__ __half g_hhi [(size_t)MB * HH];
__device__ __half g_zhi [(size_t)MB * FF];
__device__ float g_z  [(size_t)MB * FF];
__device__ float g_ps [2 * MB];     // partial exp-sums (2 column splits)
__device__ float g_pos[MB];

// ---------------- helpers ---------------------------------------------------
__device__ __forceinline__ uint32_t smem_u32(const void* p) {
    uint32_t a;
    asm("{ .reg .u64 t; cvta.to.shared.u64 t, %1; cvt.u32.u64 %0, t; }"
        : "=r"(a) : "l"(p));
    return a;
}
__device__ __forceinline__ void cp16(uint32_t s, const void* g) {
    asm volatile("cp.async.cg.shared.global [%0], [%1], 16;" :: "r"(s), "l"(g));
}
#define CP_COMMIT() asm volatile("cp.async.commit_group;")
#define CP_WAIT(n)  asm volatile("cp.async.wait_group %0;" :: "n"(n))

__device__ __forceinline__ void ldsm4(uint32_t* r, uint32_t a) {
    asm volatile("ldmatrix.sync.aligned.m8n8.x4.shared.b16 {%0,%1,%2,%3}, [%4];"
                 : "=r"(r[0]), "=r"(r[1]), "=r"(r[2]), "=r"(r[3]) : "r"(a));
}
__device__ __forceinline__ void mma_f16(float* c, const uint32_t* a,
                                        uint32_t b0, uint32_t b1) {
    asm volatile(
        "mma.sync.aligned.m16n8k16.row.col.f32.f16.f16.f32 "
        "{%0,%1,%2,%3}, {%4,%5,%6,%7}, {%8,%9}, {%0,%1,%2,%3};"
        : "+f"(c[0]), "+f"(c[1]), "+f"(c[2]), "+f"(c[3])
        : "r"(a[0]), "r"(a[1]), "r"(a[2]), "r"(a[3]), "r"(b0), "r"(b1));
}
__device__ __forceinline__ uint32_t pack2h(float a, float b) {
    __half2 t = __floats2half2_rn(a, b);
    return *reinterpret_cast<uint32_t*>(&t);
}
// fast exp on FMA/ALU pipes: y in [-45, 0.2], abs err ~1e-6
__device__ __forceinline__ float fexp(float y) {
    float t = fmaf(y, 1.4426950408889634f, 12582912.0f);
    int ki = __float_as_int(t) - 0x4B400000;
    float k = t - 12582912.0f;
    float r = fmaf(k, -0.69314718055994531f, y);
    float p = fmaf(r, 8.33333333e-3f, 4.16666667e-2f);
    p = fmaf(p, r, 1.66666667e-1f);
    p = fmaf(p, r, 5.0e-1f);
    p = fmaf(p, r, 1.0f);
    p = fmaf(p, r, 1.0f);
    return __int_as_float(__float_as_int(p) + (ki << 23));
}

// ---------------------------------------------------------------------------
// prep: fp32 -> fp16 convert (features); transpose(+optional lo) for weights
// ---------------------------------------------------------------------------
__global__ void cvt_k(const float* __restrict__ X, __half* __restrict__ Hi, size_t n)
{
    size_t stride = (size_t)gridDim.x * blockDim.x * 4;
    for (size_t i = ((size_t)blockIdx.x * blockDim.x + threadIdx.x) * 4; i < n; i += stride) {
        float4 v = *(const float4*)(X + i);
        __half h[4] = {__float2half_rn(v.x), __float2half_rn(v.y),
                       __float2half_rn(v.z), __float2half_rn(v.w)};
        *(uint2*)(Hi + i) = *(uint2*)h;
    }
}
__global__ void tsplit_k(const float* __restrict__ W, __half* __restrict__ Thi,
                         __half* __restrict__ Tlo, int K, int N)
{
    __shared__ float t[32][33];
    int nx = blockIdx.x * 32, ky = blockIdx.y * 32;
    int tx = threadIdx.x, ty = threadIdx.y;   // 32 x 8
#pragma unroll
    for (int i = 0; i < 4; i++)
        t[ty + 8 * i][tx] = W[(size_t)(ky + ty + 8 * i) * N + nx + tx];
    __syncthreads();
#pragma unroll
    for (int i = 0; i < 4; i++) {
        float v = t[tx][ty + 8 * i];
        __half h = __float2half_rn(v);
        size_t o = (size_t)(nx + ty + 8 * i) * K + ky + tx;
        Thi[o] = h;
        if (Tlo) Tlo[o] = __float2half_rn(v - __half2float(h));
    }
}

// ---------------------------------------------------------------------------
// GEMM1: pure fp16 (single MMA term). C = relu(A @ B^T + bias).
// 128x128 block, Kc=32, 6-stage cp.async, ONE sync/iter, 2 CTAs/SM.
// stage = 2 tiles x 8KB = 16KB; 6 stages = 96KB.
// ---------------------------------------------------------------------------
__global__ __launch_bounds__(256, 2)
void hgemm1_k(const __half* __restrict__ Ahi, const __half* __restrict__ Bhi,
              const float* __restrict__ bias, int Nout, __half* __restrict__ Chi)
{
    extern __shared__ char smem[];
    const uint32_t sb = smem_u32(smem);
    const int tid = threadIdx.x;
    const int bx = blockIdx.x, by = blockIdx.y;
    const int lane = tid & 31, warp = tid >> 5;
    const int wm = warp & 1, wn = warp >> 1;
    const int quad = lane >> 3, l8 = lane & 7;

    float* bias_s = (float*)(smem + 98304);
    if (tid < 128) bias_s[tid] = bias[bx * 128 + tid];

    const int lrow = tid >> 1, lhalf = tid & 1;
    const __half* gA0 = Ahi + (size_t)(by * 128 + lrow) * KK;
    const __half* gB0 = Bhi + (size_t)(bx * 128 + lrow) * KK;
    const uint32_t lso = (uint32_t)(lrow >> 3) * 512 + (lrow & 7) * 16;

    auto load_stage = [&](int kt) {
        uint32_t st = sb + (uint32_t)(kt % 6) * 16384;
        const int kbase = kt * 32;
#pragma unroll
        for (int j = 0; j < 2; j++) {
            int kb = lhalf * 2 + j;
            uint32_t so = lso + (uint32_t)kb * 128;
            cp16(st + so,         gA0 + kbase + kb * 8);
            cp16(st + 8192 + so,  gB0 + kbase + kb * 8);
        }
        CP_COMMIT();
    };

    float acc[4][4][4];
#pragma unroll
    for (int f = 0; f < 4; f++)
#pragma unroll
        for (int n = 0; n < 4; n++)
#pragma unroll
            for (int q = 0; q < 4; q++) acc[f][n][q] = 0.f;

    const uint32_t aoff = (uint32_t)(quad & 1) * 512 + (uint32_t)(quad >> 1) * 128 + l8 * 16;
    const uint32_t boff = (uint32_t)(quad >> 1) * 512 + (uint32_t)(quad & 1) * 128 + l8 * 16;

    const int NKT = KK / 32;   // 64
    load_stage(0); load_stage(1); load_stage(2); load_stage(3); load_stage(4);
    for (int kt = 0; kt < NKT; kt++) {
        CP_WAIT(4);
        __syncthreads();
        // stage (kt+5)%6 == (kt-1)%6, consumed last iteration; safe after sync
        if (kt + 5 < NKT) load_stage(kt + 5);
        const uint32_t st = sb + (uint32_t)(kt % 6) * 16384;
#pragma unroll
        for (int ks = 0; ks < 2; ks++) {
            uint32_t ah[4][4], bh[2][4];
#pragma unroll
            for (int f = 0; f < 4; f++)
                ldsm4(ah[f], st + (uint32_t)(wm * 8 + f * 2) * 512 + ks * 256 + aoff);
#pragma unroll
            for (int p = 0; p < 2; p++)
                ldsm4(bh[p], st + 8192 + (uint32_t)(wn * 4 + p * 2) * 512 + ks * 256 + boff);
#pragma unroll
            for (int f = 0; f < 4; f++)
#pragma unroll
                for (int nf = 0; nf < 4; nf++) {
                    int p = nf >> 1, q = (nf & 1) * 2;
                    mma_f16(acc[f][nf], ah[f], bh[p][q], bh[p][q + 1]);
                }
        }
    }

    const int rsub = lane >> 2;
    const int csub = (lane & 3) * 2;
#pragma unroll
    for (int f = 0; f < 4; f++) {
        int r0 = by * 128 + wm * 64 + f * 16 + rsub;
#pragma unroll
        for (int nf = 0; nf < 4; nf++) {
            int cn = wn * 32 + nf * 8 + csub;
            float b0 = bias_s[cn], b1 = bias_s[cn + 1];
            float v00 = fmaxf(acc[f][nf][0] + b0, 0.f);
            float v01 = fmaxf(acc[f][nf][1] + b1, 0.f);
            float v10 = fmaxf(acc[f][nf][2] + b0, 0.f);
            float v11 = fmaxf(acc[f][nf][3] + b1, 0.f);
            size_t o0 = (size_t)r0 * Nout + bx * 128 + cn;
            size_t o1 = o0 + (size_t)8 * Nout;
            *(uint32_t*)(Chi + o0) = pack2h(v00, v01);
            *(uint32_t*)(Chi + o1) = pack2h(v10, v11);
        }
    }
}

// ---------------------------------------------------------------------------
// GEMM2: A fp16 single-term, B = w2 (hi+lo, 2 terms) + fused L2-normalize.
// Kc=32, 4-stage (24KB/stage), 2 CTAs/SM.
// ---------------------------------------------------------------------------
__global__ __launch_bounds__(256, 2)
void hgemm2_k(const __half* __restrict__ Ahi,
              const __half* __restrict__ Bhi, const __half* __restrict__ Blo,
              const float* __restrict__ bias,
              float* __restrict__ Zf, __half* __restrict__ Zhi,
              float* __restrict__ outz)
{
    extern __shared__ char smem[];
    const uint32_t sb = smem_u32(smem);
    const int tid = threadIdx.x;
    const int bx = blockIdx.x, by = blockIdx.y;
    const int lane = tid & 31, warp = tid >> 5;
    const int wm = warp & 1, wn = warp >> 1;
    const int quad = lane >> 3, l8 = lane & 7;

    float* bias_s = (float*)(smem + 98304);
    float* rowsq4 = (float*)(smem + 98304 + 512);
    if (tid < 128) bias_s[tid] = bias[bx * 128 + tid];

    const int lrow = tid >> 1, lhalf = tid & 1;
    const __half* gA0 = Ahi + (size_t)(by * 128 + lrow) * KK;
    const __half* gB0 = Bhi + (size_t)(bx * 128 + lrow) * KK;
    const __half* gB1 = Blo + (size_t)(bx * 128 + lrow) * KK;
    const uint32_t lso = (uint32_t)(lrow >> 3) * 512 + (lrow & 7) * 16;

    auto load_stage = [&](int kt) {
        uint32_t st = sb + (uint32_t)(kt & 3) * 24576;
        const int kbase = kt * 32;
#pragma unroll
        for (int j = 0; j < 2; j++) {
            int kb = lhalf * 2 + j;
            uint32_t so = lso + (uint32_t)kb * 128;
            cp16(st + so,          gA0 + kbase + kb * 8);
            cp16(st + 8192 + so,   gB0 + kbase + kb * 8);
            cp16(st + 16384 + so,  gB1 + kbase + kb * 8);
        }
        CP_COMMIT();
    };

    float acc[4][4][4];
#pragma unroll
    for (int f = 0; f < 4; f++)
#pragma unroll
        for (int n = 0; n < 4; n++)
#pragma unroll
            for (int q = 0; q < 4; q++) acc[f][n][q] = 0.f;

    const uint32_t aoff = (uint32_t)(quad & 1) * 512 + (uint32_t)(quad >> 1) * 128 + l8 * 16;
    const uint32_t boff = (uint32_t)(quad >> 1) * 512 + (uint32_t)(quad & 1) * 128 + l8 * 16;

    const int NKT = KK / 32;
    load_stage(0); load_stage(1); load_stage(2);
    for (int kt = 0; kt < NKT; kt++) {
        CP_WAIT(2);
        __syncthreads();
        if (kt + 3 < NKT) load_stage(kt + 3);
        const uint32_t st = sb + (uint32_t)(kt & 3) * 24576;
#pragma unroll
        for (int ks = 0; ks < 2; ks++) {
            uint32_t ah[4][4], bh[2][4], bl[2][4];
#pragma unroll
            for (int f = 0; f < 4; f++)
                ldsm4(ah[f], st + (uint32_t)(wm * 8 + f * 2) * 512 + ks * 256 + aoff);
#pragma unroll
            for (int p = 0; p < 2; p++) {
                uint32_t base = (uint32_t)(wn * 4 + p * 2) * 512 + ks * 256 + boff;
                ldsm4(bh[p], st + 8192 + base);
                ldsm4(bl[p], st + 16384 + base);
            }
#pragma unroll
            for (int f = 0; f < 4; f++)
#pragma unroll
                for (int nf = 0; nf < 4; nf++) {
                    int p = nf >> 1, q = (nf & 1) * 2;
                    mma_f16(acc[f][nf], ah[f], bh[p][q], bh[p][q + 1]);
                    mma_f16(acc[f][nf], ah[f], bl[p][q], bl[p][q + 1]);
                }
        }
    }

    const int rsub = lane >> 2;
    const int csub = (lane & 3) * 2;
#pragma unroll
    for (int f = 0; f < 4; f++) {
        float s0 = 0.f, s1 = 0.f;
#pragma unroll
        for (int nf = 0; nf < 4; nf++) {
            int cn = wn * 32 + nf * 8 + csub;
            float b0 = bias_s[cn], b1 = bias_s[cn + 1];
            float v00 = acc[f][nf][0] + b0, v01 = acc[f][nf][1] + b1;
            float v10 = acc[f][nf][2] + b0, v11 = acc[f][nf][3] + b1;
            s0 += v00 * v00 + v01 * v01;
            s1 += v10 * v10 + v11 * v11;
        }
        s0 += __shfl_xor_sync(0xffffffffu, s0, 1);
        s0 += __shfl_xor_sync(0xffffffffu, s0, 2);
        s1 += __shfl_xor_sync(0xffffffffu, s1, 1);
        s1 += __shfl_xor_sync(0xffffffffu, s1, 2);
        if ((lane & 3) == 0) {
            int lr = wm * 64 + f * 16 + rsub;
            rowsq4[wn * 128 + lr] = s0;
            rowsq4[wn * 128 + lr + 8] = s1;
        }
    }
    __syncthreads();
#pragma unroll
    for (int f = 0; f < 4; f++) {
        int lr0 = wm * 64 + f * 16 + rsub;
        float sq0 = rowsq4[lr0] + rowsq4[128 + lr0] + rowsq4[256 + lr0] + rowsq4[384 + lr0];
        float sq1 = rowsq4[lr0 + 8] + rowsq4[128 + lr0 + 8] + rowsq4[256 + lr0 + 8] + rowsq4[384 + lr0 + 8];
        float inv0 = rsqrtf(fmaxf(sq0, 1e-24f));
        float inv1 = rsqrtf(fmaxf(sq1, 1e-24f));
        int r0 = by * 128 + lr0;
#pragma unroll
        for (int nf = 0; nf < 4; nf++) {
            int cn = wn * 32 + nf * 8 + csub;
            float b0 = bias_s[cn], b1 = bias_s[cn + 1];
            float z00 = (acc[f][nf][0] + b0) * inv0, z01 = (acc[f][nf][1] + b1) * inv0;
            float z10 = (acc[f][nf][2] + b0) * inv1, z11 = (acc[f][nf][3] + b1) * inv1;
            size_t o0 = (size_t)r0 * FF + cn;
            size_t o1 = o0 + (size_t)8 * FF;
            *(float2*)(Zf + o0) = make_float2(z00, z01);
            *(float2*)(Zf + o1) = make_float2(z10, z11);
            if (outz) {   // d_out+1 only 4B aligned: scalar stores
                outz[o0] = z00; outz[o0 + 1] = z01;
                outz[o1] = z10; outz[o1 + 1] = z11;
            }
            *(uint32_t*)(Zhi + o0) = pack2h(z00, z01);
            *(uint32_t*)(Zhi + o1) = pack2h(z10, z11);
        }
    }
}

// ---------------------------------------------------------------------------
// HMMA masked exp-sum: grid (2 col-splits, 128 row-blocks), fp16 hi-only sim.
// ---------------------------------------------------------------------------
__global__ __launch_bounds__(256, 2)
void lse_hmma_k(const __half* __restrict__ Zhi, float* __restrict__ ps)
{
    extern __shared__ char smem[];
    const uint32_t sb = smem_u32(smem);
    const int tid = threadIdx.x;
    const int split = blockIdx.x, by = blockIdx.y;
    const int lane = tid & 31, warp = tid >> 5;
    const int wm = warp & 1, wn = warp >> 1;
    const int quad = lane >> 3, l8 = lane & 7;

    float* lsum4 = (float*)(smem + 98304);

    const int lrow = tid >> 1, lhalf = tid & 1;
    const uint32_t lso = (uint32_t)(lrow >> 3) * 2048 + (lrow & 7) * 16;

    {
        const __half* ga = Zhi + (size_t)(by * 128 + lrow) * FF;
#pragma unroll
        for (int j = 0; j < 8; j++) {
            int kb = lhalf * 8 + j;
            cp16(sb + lso + kb * 128, ga + kb * 8);
        }
    }
    auto loadB = [&](int bxt, int s) {
        uint32_t st = sb + 32768 + (uint32_t)s * 32768;
        const __half* gb = Zhi + (size_t)(bxt * 128 + lrow) * FF;
#pragma unroll
        for (int j = 0; j < 8; j++) {
            int kb = lhalf * 8 + j;
            cp16(st + lso + kb * 128, gb + kb * 8);
        }
        CP_COMMIT();
    };
    const int bx0 = split * 64;
    loadB(bx0, 0);   // commits A too

    float rs[4][2];
#pragma unroll
    for (int f = 0; f < 4; f++) { rs[f][0] = 0.f; rs[f][1] = 0.f; }

    const uint32_t aoff = (uint32_t)(quad & 1) * 2048 + (uint32_t)(quad >> 1) * 128 + l8 * 16;
    const uint32_t boff = (uint32_t)(quad >> 1) * 2048 + (uint32_t)(quad & 1) * 128 + l8 * 16;
    const int rsub = lane >> 2;
    const int csub = (lane & 3) * 2;

    for (int i = 0; i < 64; i++) {
        const int bxt = bx0 + i;
        const int s = i & 1;
        CP_WAIT(0);
        __syncthreads();
        if (i < 63) loadB(bx0 + i + 1, s ^ 1);

        float acc[4][4][4];
#pragma unroll
        for (int f = 0; f < 4; f++)
#pragma unroll
            for (int n = 0; n < 4; n++)
#pragma unroll
                for (int q = 0; q < 4; q++) acc[f][n][q] = 0.f;

        const uint32_t stB = sb + 32768 + (uint32_t)s * 32768;
#pragma unroll
        for (int ks = 0; ks < 8; ks++) {
            uint32_t ah[4][4], bh[2][4];
#pragma unroll
            for (int f = 0; f < 4; f++)
                ldsm4(ah[f], sb + (uint32_t)(wm * 8 + f * 2) * 2048 + ks * 256 + aoff);
#pragma unroll
            for (int p = 0; p < 2; p++)
                ldsm4(bh[p], stB + (uint32_t)(wn * 4 + p * 2) * 2048 + ks * 256 + boff);
#pragma unroll
            for (int f = 0; f < 4; f++)
#pragma unroll
                for (int nf = 0; nf < 4; nf++) {
                    int p = nf >> 1, q = (nf & 1) * 2;
                    mma_f16(acc[f][nf], ah[f], bh[p][q], bh[p][q + 1]);
                }
        }

        const bool diag = (bxt == by);
#pragma unroll
        for (int f = 0; f < 4; f++) {
#pragma unroll
            for (int nf = 0; nf < 4; nf++) {
                float e00 = fexp(fmaf(acc[f][nf][0], INV_T, -INV_T));
                float e01 = fexp(fmaf(acc[f][nf][1], INV_T, -INV_T));
                float e10 = fexp(fmaf(acc[f][nf][2], INV_T, -INV_T));
                float e11 = fexp(fmaf(acc[f][nf][3], INV_T, -INV_T));
                if (diag) {
                    int lr = wm * 64 + f * 16 + rsub;
                    int lc = wn * 32 + nf * 8 + csub;
                    if (lr == lc)         e00 = 0.f;
                    if (lr == lc + 1)     e01 = 0.f;
                    if (lr + 8 == lc)     e10 = 0.f;
                    if (lr + 8 == lc + 1) e11 = 0.f;
                }
                rs[f][0] += e00 + e01;
                rs[f][1] += e10 + e11;
            }
        }
    }

#pragma unroll
    for (int f = 0; f < 4; f++) {
#pragma unroll
        for (int h = 0; h < 2; h++) {
            float v = rs[f][h];
            v += __shfl_xor_sync(0xffffffffu, v, 1);
            v += __shfl_xor_sync(0xffffffffu, v, 2);
            if ((lane & 3) == 0)
                lsum4[wn * 128 + wm * 64 + f * 16 + h * 8 + rsub] = v;
        }
    }
    __syncthreads();
    if (tid < 128) {
        float tot = lsum4[tid] + lsum4[128 + tid] + lsum4[256 + tid] + lsum4[384 + tid];
        ps[(size_t)split * MB + by * 128 + tid] = tot;
    }
}

// ---------------------------------------------------------------------------
__global__ void pos_k(const float* __restrict__ Z, float* __restrict__ pos)
{
    const int row = blockIdx.x;
    const int t = threadIdx.x;
    const int prow = (row + MB / 2) & (MB - 1);
    float s = Z[(size_t)row * FF + t] * Z[(size_t)prow * FF + t];
#pragma unroll
    for (int o = 16; o; o >>= 1) s += __shfl_xor_sync(0xffffffffu, s, o);
    __shared__ float ws[4];
    if ((t & 31) == 0) ws[t >> 5] = s;
    __syncthreads();
    if (t == 0) pos[row] = (ws[0] + ws[1] + ws[2] + ws[3]) * INV_T;
}

__global__ void loss_k(const float* __restrict__ ps, const float* __restrict__ pos,
                       float* __restrict__ out)
{
    __shared__ float sm[256];
    const int t = threadIdx.x;
    float s = 0.f;
    for (int i = t; i < MB; i += 256) {
        float tot = ps[i] + ps[MB + i];
        s += logf(tot) + INV_T - pos[i];
    }
    sm[t] = s;
    __syncthreads();
    for (int o = 128; o; o >>= 1) {
        if (t < o) sm[t] += sm[t + o];
        __syncthreads();
    }
    if (t == 0) out[0] = sm[0] * (1.0f / MB);
}

// ---------------------------------------------------------------------------
extern "C" void kernel_launch(void* const* d_in, const int* in_sizes, int n_in,
                              void* d_out, int out_size)
{
    const float* features = (const float*)d_in[0];
    const float* w1 = (const float*)d_in[1];
    const float* b1 = (const float*)d_in[2];
    const float* w2 = (const float*)d_in[3];
    const float* b2 = (const float*)d_in[4];
    float* out = (float*)d_out;

    __half *fhi, *w1hi, *w2hi, *w2lo, *hhi, *zhi;
    float *z, *psb, *posb;
    cudaGetSymbolAddress((void**)&fhi,  g_fhi);
    cudaGetSymbolAddress((void**)&w1hi, g_w1hi);
    cudaGetSymbolAddress((void**)&w2hi, g_w2hi);
    cudaGetSymbolAddress((void**)&w2lo, g_w2lo);
    cudaGetSymbolAddress((void**)&hhi,  g_hhi);
    cudaGetSymbolAddress((void**)&zhi,  g_zhi);
    cudaGetSymbolAddress((void**)&z,    g_z);
    cudaGetSymbolAddress((void**)&psb,  g_ps);
    cudaGetSymbolAddress((void**)&posb, g_pos);

    const int SM_G1 = 98304 + 512;          // 6 stages x 16KB + bias
    const int SM_G2 = 98304 + 512 + 2048;   // 4 stages x 24KB + bias + rowsq
    const int SM_L  = 98304 + 2048;         // A + 2 B stages + lsum
    cudaFuncSetAttribute(hgemm1_k,  cudaFuncAttributeMaxDynamicSharedMemorySize, SM_G1);
    cudaFuncSetAttribute(hgemm2_k,  cudaFuncAttributeMaxDynamicSharedMemorySize, SM_G2);
    cudaFuncSetAttribute(lse_hmma_k, cudaFuncAttributeMaxDynamicSharedMemorySize, SM_L);

    // prep
    cvt_k<<<1024, 256>>>(features, fhi, (size_t)MB * DD);
    tsplit_k<<<dim3(HH / 32, DD / 32), dim3(32, 8)>>>(w1, w1hi, nullptr, DD, HH);
    tsplit_k<<<dim3(FF / 32, HH / 32), dim3(32, 8)>>>(w2, w2hi, w2lo, HH, FF);

    // 1) h = relu(features @ w1 + b1), pure fp16
    hgemm1_k<<<dim3(HH / 128, MB / 128), 256, SM_G1>>>(fhi, w1hi, b1, HH, hhi);

    // 2) p = h @ w2 + b2 (w2 2-term), fused L2-normalize
    float* outz = (out_size >= 1 + MB * FF) ? (out + 1) : nullptr;
    hgemm2_k<<<dim3(1, MB / 128), 256, SM_G2>>>(hhi, w2hi, w2lo, b2, z, zhi, outz);

    // 3) pos, 4) masked exp-sums, 5) loss
    pos_k<<<MB, 128>>>(z, posb);
    lse_hmma_k<<<dim3(2, MB / 128), 256, SM_L>>>(zhi, psb);
    loss_k<<<1, 256>>>(psb, posb, out);
}

// round 9
// speedup vs baseline: 6.2499x; 1.0005x over previous
#include <cuda_runtime.h>
#include <cuda_fp16.h>
#include <math.h>
#include <stdint.h>

#define MB 16384   // rows (2N)
#define DD 2048
#define HH 2048
#define FF 128
#define KK 2048    // K of both big GEMMs

constexpr float INV_T = 1.0f / 0.07f;
constexpr float C_EX2 = 20.6099773964f;   // INV_T * log2(e)

// ---------------- scratch --------------------------------------------------
__device__ __half g_fhi [(size_t)MB * DD];
__device__ __half g_w1hi[(size_t)HH * DD];
__device__ __half g_w2hi[(size_t)FF * HH];
__device__ __half g_w2lo[(size_t)FF * HH];
__device__ __half g_hhi [(size_t)MB * HH];
__device__ __half g_zhi [(size_t)MB * FF];
__device__ float g_z  [(size_t)MB * FF];
__device__ float g_ps [2 * MB];
__device__ float g_pos[MB];

// ---------------- helpers ---------------------------------------------------
__device__ __forceinline__ uint32_t smem_u32(const void* p) {
    uint32_t a;
    asm("{ .reg .u64 t; cvta.to.shared.u64 t, %1; cvt.u32.u64 %0, t; }"
        : "=r"(a) : "l"(p));
    return a;
}
__device__ __forceinline__ void cp16(uint32_t s, const void* g) {
    asm volatile("cp.async.cg.shared.global [%0], [%1], 16;" :: "r"(s), "l"(g));
}
#define CP_COMMIT() asm volatile("cp.async.commit_group;")
#define CP_WAIT(n)  asm volatile("cp.async.wait_group %0;" :: "n"(n))

__device__ __forceinline__ void ldsm4(uint32_t* r, uint32_t a) {
    asm volatile("ldmatrix.sync.aligned.m8n8.x4.shared.b16 {%0,%1,%2,%3}, [%4];"
                 : "=r"(r[0]), "=r"(r[1]), "=r"(r[2]), "=r"(r[3]) : "r"(a));
}
__device__ __forceinline__ void mma_f16(float* c, const uint32_t* a,
                                        uint32_t b0, uint32_t b1) {
    asm volatile(
        "mma.sync.aligned.m16n8k16.row.col.f32.f16.f16.f32 "
        "{%0,%1,%2,%3}, {%4,%5,%6,%7}, {%8,%9}, {%0,%1,%2,%3};"
        : "+f"(c[0]), "+f"(c[1]), "+f"(c[2]), "+f"(c[3])
        : "r"(a[0]), "r"(a[1]), "r"(a[2]), "r"(a[3]), "r"(b0), "r"(b1));
}
__device__ __forceinline__ uint32_t pack2h(float a, float b) {
    __half2 t = __floats2half2_rn(a, b);
    return *reinterpret_cast<uint32_t*>(&t);
}
// exp via MUFU: e^((acc-1)*INV_T) = 2^(acc*C - C); 1 FFMA + 1 MUFU.
__device__ __forceinline__ float ex2f(float x) {
    float r;
    asm("ex2.approx.f32 %0, %1;" : "=f"(r) : "f"(x));
    return r;
}

// ---------------------------------------------------------------------------
// prep
// ---------------------------------------------------------------------------
__global__ void cvt_k(const float* __restrict__ X, __half* __restrict__ Hi, size_t n)
{
    size_t stride = (size_t)gridDim.x * blockDim.x * 4;
    for (size_t i = ((size_t)blockIdx.x * blockDim.x + threadIdx.x) * 4; i < n; i += stride) {
        float4 v = *(const float4*)(X + i);
        __half h[4] = {__float2half_rn(v.x), __float2half_rn(v.y),
                       __float2half_rn(v.z), __float2half_rn(v.w)};
        *(uint2*)(Hi + i) = *(uint2*)h;
    }
}
__global__ void tsplit_k(const float* __restrict__ W, __half* __restrict__ Thi,
                         __half* __restrict__ Tlo, int K, int N)
{
    __shared__ float t[32][33];
    int nx = blockIdx.x * 32, ky = blockIdx.y * 32;
    int tx = threadIdx.x, ty = threadIdx.y;   // 32 x 8
#pragma unroll
    for (int i = 0; i < 4; i++)
        t[ty + 8 * i][tx] = W[(size_t)(ky + ty + 8 * i) * N + nx + tx];
    __syncthreads();
#pragma unroll
    for (int i = 0; i < 4; i++) {
        float v = t[tx][ty + 8 * i];
        __half h = __float2half_rn(v);
        size_t o = (size_t)(nx + ty + 8 * i) * K + ky + tx;
        Thi[o] = h;
        if (Tlo) Tlo[o] = __float2half_rn(v - __half2float(h));
    }
}

// ---------------------------------------------------------------------------
// GEMM1: pure fp16. C = relu(A @ B^T + bias). 128x128, Kc=32, 6-stage.
// ---------------------------------------------------------------------------
__global__ __launch_bounds__(256, 2)
void hgemm1_k(const __half* __restrict__ Ahi, const __half* __restrict__ Bhi,
              const float* __restrict__ bias, int Nout, __half* __restrict__ Chi)
{
    extern __shared__ char smem[];
    const uint32_t sb = smem_u32(smem);
    const int tid = threadIdx.x;
    const int bx = blockIdx.x, by = blockIdx.y;
    const int lane = tid & 31, warp = tid >> 5;
    const int wm = warp & 1, wn = warp >> 1;
    const int quad = lane >> 3, l8 = lane & 7;

    float* bias_s = (float*)(smem + 98304);
    if (tid < 128) bias_s[tid] = bias[bx * 128 + tid];

    const int lrow = tid >> 1, lhalf = tid & 1;
    const __half* gA0 = Ahi + (size_t)(by * 128 + lrow) * KK;
    const __half* gB0 = Bhi + (size_t)(bx * 128 + lrow) * KK;
    const uint32_t lso = (uint32_t)(lrow >> 3) * 512 + (lrow & 7) * 16;

    auto load_stage = [&](int kt) {
        uint32_t st = sb + (uint32_t)(kt % 6) * 16384;
        const int kbase = kt * 32;
#pragma unroll
        for (int j = 0; j < 2; j++) {
            int kb = lhalf * 2 + j;
            uint32_t so = lso + (uint32_t)kb * 128;
            cp16(st + so,         gA0 + kbase + kb * 8);
            cp16(st + 8192 + so,  gB0 + kbase + kb * 8);
        }
        CP_COMMIT();
    };

    float acc[4][4][4];
#pragma unroll
    for (int f = 0; f < 4; f++)
#pragma unroll
        for (int n = 0; n < 4; n++)
#pragma unroll
            for (int q = 0; q < 4; q++) acc[f][n][q] = 0.f;

    const uint32_t aoff = (uint32_t)(quad & 1) * 512 + (uint32_t)(quad >> 1) * 128 + l8 * 16;
    const uint32_t boff = (uint32_t)(quad >> 1) * 512 + (uint32_t)(quad & 1) * 128 + l8 * 16;

    const int NKT = KK / 32;   // 64
    load_stage(0); load_stage(1); load_stage(2); load_stage(3); load_stage(4);
    for (int kt = 0; kt < NKT; kt++) {
        CP_WAIT(4);
        __syncthreads();
        if (kt + 5 < NKT) load_stage(kt + 5);
        const uint32_t st = sb + (uint32_t)(kt % 6) * 16384;
#pragma unroll
        for (int ks = 0; ks < 2; ks++) {
            uint32_t ah[4][4], bh[2][4];
#pragma unroll
            for (int f = 0; f < 4; f++)
                ldsm4(ah[f], st + (uint32_t)(wm * 8 + f * 2) * 512 + ks * 256 + aoff);
#pragma unroll
            for (int p = 0; p < 2; p++)
                ldsm4(bh[p], st + 8192 + (uint32_t)(wn * 4 + p * 2) * 512 + ks * 256 + boff);
#pragma unroll
            for (int f = 0; f < 4; f++)
#pragma unroll
                for (int nf = 0; nf < 4; nf++) {
                    int p = nf >> 1, q = (nf & 1) * 2;
                    mma_f16(acc[f][nf], ah[f], bh[p][q], bh[p][q + 1]);
                }
        }
    }

    const int rsub = lane >> 2;
    const int csub = (lane & 3) * 2;
#pragma unroll
    for (int f = 0; f < 4; f++) {
        int r0 = by * 128 + wm * 64 + f * 16 + rsub;
#pragma unroll
        for (int nf = 0; nf < 4; nf++) {
            int cn = wn * 32 + nf * 8 + csub;
            float b0 = bias_s[cn], b1 = bias_s[cn + 1];
            float v00 = fmaxf(acc[f][nf][0] + b0, 0.f);
            float v01 = fmaxf(acc[f][nf][1] + b1, 0.f);
            float v10 = fmaxf(acc[f][nf][2] + b0, 0.f);
            float v11 = fmaxf(acc[f][nf][3] + b1, 0.f);
            size_t o0 = (size_t)r0 * Nout + bx * 128 + cn;
            size_t o1 = o0 + (size_t)8 * Nout;
            *(uint32_t*)(Chi + o0) = pack2h(v00, v01);
            *(uint32_t*)(Chi + o1) = pack2h(v10, v11);
        }
    }
}

// ---------------------------------------------------------------------------
// GEMM2: 64-row tiles (grid 256 -> full chip). A fp16, B = w2 hi+lo (2 terms),
// fused L2-normalize. Kc=32, 4-stage x 20KB, 2 CTAs/SM.
// Warps 2x4: warp tile 32x32. acc[2][4][4].
// ---------------------------------------------------------------------------
__global__ __launch_bounds__(256, 2)
void hgemm2_k(const __half* __restrict__ Ahi,
              const __half* __restrict__ Bhi, const __half* __restrict__ Blo,
              const float* __restrict__ bias,
              float* __restrict__ Zf, __half* __restrict__ Zhi,
              float* __restrict__ outz)
{
    extern __shared__ char smem[];
    const uint32_t sb = smem_u32(smem);
    const int tid = threadIdx.x;
    const int by = blockIdx.y;
    const int lane = tid & 31, warp = tid >> 5;
    const int wm = warp & 1, wn = warp >> 1;
    const int quad = lane >> 3, l8 = lane & 7;

    float* bias_s = (float*)(smem + 81920);
    float* rowsq4 = (float*)(smem + 81920 + 512);   // [4][64]
    if (tid < 128) bias_s[tid] = bias[tid];

    // A loader: 1 cp16/thread; B loaders: 2 each hi/lo
    const int arow = tid >> 2, akb = tid & 3;
    const uint32_t aso = (uint32_t)(arow >> 3) * 512 + (arow & 7) * 16 + akb * 128;
    const __half* gA0 = Ahi + (size_t)(by * 64 + arow) * KK + akb * 8;
    const int lrow = tid >> 1, lhalf = tid & 1;
    const uint32_t lso = (uint32_t)(lrow >> 3) * 512 + (lrow & 7) * 16;
    const __half* gB0 = Bhi + (size_t)lrow * KK;
    const __half* gB1 = Blo + (size_t)lrow * KK;

    auto load_stage = [&](int kt) {
        uint32_t st = sb + (uint32_t)(kt & 3) * 20480;
        const int kbase = kt * 32;
        cp16(st + aso, gA0 + kbase);
#pragma unroll
        for (int j = 0; j < 2; j++) {
            int kb = lhalf * 2 + j;
            uint32_t so = lso + (uint32_t)kb * 128;
            cp16(st + 4096 + so,   gB0 + kbase + kb * 8);
            cp16(st + 12288 + so,  gB1 + kbase + kb * 8);
        }
        CP_COMMIT();
    };

    float acc[2][4][4];
#pragma unroll
    for (int f = 0; f < 2; f++)
#pragma unroll
        for (int n = 0; n < 4; n++)
#pragma unroll
            for (int q = 0; q < 4; q++) acc[f][n][q] = 0.f;

    const uint32_t aoff = (uint32_t)(quad & 1) * 512 + (uint32_t)(quad >> 1) * 128 + l8 * 16;
    const uint32_t boff = (uint32_t)(quad >> 1) * 512 + (uint32_t)(quad & 1) * 128 + l8 * 16;

    const int NKT = KK / 32;
    load_stage(0); load_stage(1); load_stage(2);
    for (int kt = 0; kt < NKT; kt++) {
        CP_WAIT(2);
        __syncthreads();
        if (kt + 3 < NKT) load_stage(kt + 3);
        const uint32_t st = sb + (uint32_t)(kt & 3) * 20480;
#pragma unroll
        for (int ks = 0; ks < 2; ks++) {
            uint32_t ah[2][4], bh[2][4], bl[2][4];
#pragma unroll
            for (int f = 0; f < 2; f++)
                ldsm4(ah[f], st + (uint32_t)(wm * 4 + f * 2) * 512 + ks * 256 + aoff);
#pragma unroll
            for (int p = 0; p < 2; p++) {
                uint32_t base = (uint32_t)(wn * 4 + p * 2) * 512 + ks * 256 + boff;
                ldsm4(bh[p], st + 4096 + base);
                ldsm4(bl[p], st + 12288 + base);
            }
#pragma unroll
            for (int f = 0; f < 2; f++)
#pragma unroll
                for (int nf = 0; nf < 4; nf++) {
                    int p = nf >> 1, q = (nf & 1) * 2;
                    mma_f16(acc[f][nf], ah[f], bh[p][q], bh[p][q + 1]);
                    mma_f16(acc[f][nf], ah[f], bl[p][q], bl[p][q + 1]);
                }
        }
    }

    const int rsub = lane >> 2;
    const int csub = (lane & 3) * 2;
#pragma unroll
    for (int f = 0; f < 2; f++) {
        float s0 = 0.f, s1 = 0.f;
#pragma unroll
        for (int nf = 0; nf < 4; nf++) {
            int cn = wn * 32 + nf * 8 + csub;
            float b0 = bias_s[cn], b1 = bias_s[cn + 1];
            float v00 = acc[f][nf][0] + b0, v01 = acc[f][nf][1] + b1;
            float v10 = acc[f][nf][2] + b0, v11 = acc[f][nf][3] + b1;
            s0 += v00 * v00 + v01 * v01;
            s1 += v10 * v10 + v11 * v11;
        }
        s0 += __shfl_xor_sync(0xffffffffu, s0, 1);
        s0 += __shfl_xor_sync(0xffffffffu, s0, 2);
        s1 += __shfl_xor_sync(0xffffffffu, s1, 1);
        s1 += __shfl_xor_sync(0xffffffffu, s1, 2);
        if ((lane & 3) == 0) {
            int lr = wm * 32 + f * 16 + rsub;
            rowsq4[wn * 64 + lr] = s0;
            rowsq4[wn * 64 + lr + 8] = s1;
        }
    }
    __syncthreads();
#pragma unroll
    for (int f = 0; f < 2; f++) {
        int lr0 = wm * 32 + f * 16 + rsub;
        float sq0 = rowsq4[lr0] + rowsq4[64 + lr0] + rowsq4[128 + lr0] + rowsq4[192 + lr0];
        float sq1 = rowsq4[lr0 + 8] + rowsq4[64 + lr0 + 8] + rowsq4[128 + lr0 + 8] + rowsq4[192 + lr0 + 8];
        float inv0 = rsqrtf(fmaxf(sq0, 1e-24f));
        float inv1 = rsqrtf(fmaxf(sq1, 1e-24f));
        int r0 = by * 64 + lr0;
#pragma unroll
        for (int nf = 0; nf < 4; nf++) {
            int cn = wn * 32 + nf * 8 + csub;
            float b0 = bias_s[cn], b1 = bias_s[cn + 1];
            float z00 = (acc[f][nf][0] + b0) * inv0, z01 = (acc[f][nf][1] + b1) * inv0;
            float z10 = (acc[f][nf][2] + b0) * inv1, z11 = (acc[f][nf][3] + b1) * inv1;
            size_t o0 = (size_t)r0 * FF + cn;
            size_t o1 = o0 + (size_t)8 * FF;
            *(float2*)(Zf + o0) = make_float2(z00, z01);
            *(float2*)(Zf + o1) = make_float2(z10, z11);
            if (outz) {   // d_out+1 only 4B aligned: scalar stores
                outz[o0] = z00; outz[o0 + 1] = z01;
                outz[o1] = z10; outz[o1 + 1] = z11;
            }
            *(uint32_t*)(Zhi + o0) = pack2h(z00, z01);
            *(uint32_t*)(Zhi + o1) = pack2h(z10, z11);
        }
    }
}

// ---------------------------------------------------------------------------
// HMMA masked exp-sum: grid (2 col-splits, 128 row-blocks); MUFU exp.
// ---------------------------------------------------------------------------
__global__ __launch_bounds__(256, 2)
void lse_hmma_k(const __half* __restrict__ Zhi, float* __restrict__ ps)
{
    extern __shared__ char smem[];
    const uint32_t sb = smem_u32(smem);
    const int tid = threadIdx.x;
    const int split = blockIdx.x, by = blockIdx.y;
    const int lane = tid & 31, warp = tid >> 5;
    const int wm = warp & 1, wn = warp >> 1;
    const int quad = lane >> 3, l8 = lane & 7;

    float* lsum4 = (float*)(smem + 98304);

    const int lrow = tid >> 1, lhalf = tid & 1;
    const uint32_t lso = (uint32_t)(lrow >> 3) * 2048 + (lrow & 7) * 16;

    {
        const __half* ga = Zhi + (size_t)(by * 128 + lrow) * FF;
#pragma unroll
        for (int j = 0; j < 8; j++) {
            int kb = lhalf * 8 + j;
            cp16(sb + lso + kb * 128, ga + kb * 8);
        }
    }
    auto loadB = [&](int bxt, int s) {
        uint32_t st = sb + 32768 + (uint32_t)s * 32768;
        const __half* gb = Zhi + (size_t)(bxt * 128 + lrow) * FF;
#pragma unroll
        for (int j = 0; j < 8; j++) {
            int kb = lhalf * 8 + j;
            cp16(st + lso + kb * 128, gb + kb * 8);
        }
        CP_COMMIT();
    };
    const int bx0 = split * 64;
    loadB(bx0, 0);   // commits A too

    float rs[4][2];
#pragma unroll
    for (int f = 0; f < 4; f++) { rs[f][0] = 0.f; rs[f][1] = 0.f; }

    const uint32_t aoff = (uint32_t)(quad & 1) * 2048 + (uint32_t)(quad >> 1) * 128 + l8 * 16;
    const uint32_t boff = (uint32_t)(quad >> 1) * 2048 + (uint32_t)(quad & 1) * 128 + l8 * 16;
    const int rsub = lane >> 2;
    const int csub = (lane & 3) * 2;

    for (int i = 0; i < 64; i++) {
        const int bxt = bx0 + i;
        const int s = i & 1;
        CP_WAIT(0);
        __syncthreads();
        if (i < 63) loadB(bx0 + i + 1, s ^ 1);

        float acc[4][4][4];
#pragma unroll
        for (int f = 0; f < 4; f++)
#pragma unroll
            for (int n = 0; n < 4; n++)
#pragma unroll
                for (int q = 0; q < 4; q++) acc[f][n][q] = 0.f;

        const uint32_t stB = sb + 32768 + (uint32_t)s * 32768;
#pragma unroll
        for (int ks = 0; ks < 8; ks++) {
            uint32_t ah[4][4], bh[2][4];
#pragma unroll
            for (int f = 0; f < 4; f++)
                ldsm4(ah[f], sb + (uint32_t)(wm * 8 + f * 2) * 2048 + ks * 256 + aoff);
#pragma unroll
            for (int p = 0; p < 2; p++)
                ldsm4(bh[p], stB + (uint32_t)(wn * 4 + p * 2) * 2048 + ks * 256 + boff);
#pragma unroll
            for (int f = 0; f < 4; f++)
#pragma unroll
                for (int nf = 0; nf < 4; nf++) {
                    int p = nf >> 1, q = (nf & 1) * 2;
                    mma_f16(acc[f][nf], ah[f], bh[p][q], bh[p][q + 1]);
                }
        }

        const bool diag = (bxt == by);
#pragma unroll
        for (int f = 0; f < 4; f++) {
#pragma unroll
            for (int nf = 0; nf < 4; nf++) {
                float e00 = ex2f(fmaf(acc[f][nf][0], C_EX2, -C_EX2));
                float e01 = ex2f(fmaf(acc[f][nf][1], C_EX2, -C_EX2));
                float e10 = ex2f(fmaf(acc[f][nf][2], C_EX2, -C_EX2));
                float e11 = ex2f(fmaf(acc[f][nf][3], C_EX2, -C_EX2));
                if (diag) {
                    int lr = wm * 64 + f * 16 + rsub;
                    int lc = wn * 32 + nf * 8 + csub;
                    if (lr == lc)         e00 = 0.f;
                    if (lr == lc + 1)     e01 = 0.f;
                    if (lr + 8 == lc)     e10 = 0.f;
                    if (lr + 8 == lc + 1) e11 = 0.f;
                }
                rs[f][0] += e00 + e01;
                rs[f][1] += e10 + e11;
            }
        }
    }

#pragma unroll
    for (int f = 0; f < 4; f++) {
#pragma unroll
        for (int h = 0; h < 2; h++) {
            float v = rs[f][h];
            v += __shfl_xor_sync(0xffffffffu, v, 1);
            v += __shfl_xor_sync(0xffffffffu, v, 2);
            if ((lane & 3) == 0)
                lsum4[wn * 128 + wm * 64 + f * 16 + h * 8 + rsub] = v;
        }
    }
    __syncthreads();
    if (tid < 128) {
        float tot = lsum4[tid] + lsum4[128 + tid] + lsum4[256 + tid] + lsum4[384 + tid];
        ps[(size_t)split * MB + by * 128 + tid] = tot;
    }
}

// ---------------------------------------------------------------------------
__global__ void pos_k(const float* __restrict__ Z, float* __restrict__ pos)
{
    const int row = blockIdx.x;
    const int t = threadIdx.x;
    const int prow = (row + MB / 2) & (MB - 1);
    float s = Z[(size_t)row * FF + t] * Z[(size_t)prow * FF + t];
#pragma unroll
    for (int o = 16; o; o >>= 1) s += __shfl_xor_sync(0xffffffffu, s, o);
    __shared__ float ws[4];
    if ((t & 31) == 0) ws[t >> 5] = s;
    __syncthreads();
    if (t == 0) pos[row] = (ws[0] + ws[1] + ws[2] + ws[3]) * INV_T;
}

__global__ void loss_k(const float* __restrict__ ps, const float* __restrict__ pos,
                       float* __restrict__ out)
{
    __shared__ float sm[256];
    const int t = threadIdx.x;
    float s = 0.f;
    for (int i = t; i < MB; i += 256) {
        float tot = ps[i] + ps[MB + i];
        s += logf(tot) + INV_T - pos[i];
    }
    sm[t] = s;
    __syncthreads();
    for (int o = 128; o; o >>= 1) {
        if (t < o) sm[t] += sm[t + o];
        __syncthreads();
    }
    if (t == 0) out[0] = sm[0] * (1.0f / MB);
}

// ---------------------------------------------------------------------------
extern "C" void kernel_launch(void* const* d_in, const int* in_sizes, int n_in,
                              void* d_out, int out_size)
{
    const float* features = (const float*)d_in[0];
    const float* w1 = (const float*)d_in[1];
    const float* b1 = (const float*)d_in[2];
    const float* w2 = (const float*)d_in[3];
    const float* b2 = (const float*)d_in[4];
    float* out = (float*)d_out;

    __half *fhi, *w1hi, *w2hi, *w2lo, *hhi, *zhi;
    float *z, *psb, *posb;
    cudaGetSymbolAddress((void**)&fhi,  g_fhi);
    cudaGetSymbolAddress((void**)&w1hi, g_w1hi);
    cudaGetSymbolAddress((void**)&w2hi, g_w2hi);
    cudaGetSymbolAddress((void**)&w2lo, g_w2lo);
    cudaGetSymbolAddress((void**)&hhi,  g_hhi);
    cudaGetSymbolAddress((void**)&zhi,  g_zhi);
    cudaGetSymbolAddress((void**)&z,    g_z);
    cudaGetSymbolAddress((void**)&psb,  g_ps);
    cudaGetSymbolAddress((void**)&posb, g_pos);

    const int SM_G1 = 98304 + 512;           // 6 stages x 16KB + bias
    const int SM_G2 = 81920 + 512 + 1024;    // 4 stages x 20KB + bias + rowsq
    const int SM_L  = 98304 + 2048;          // A + 2 B stages + lsum
    cudaFuncSetAttribute(hgemm1_k,  cudaFuncAttributeMaxDynamicSharedMemorySize, SM_G1);
    cudaFuncSetAttribute(hgemm2_k,  cudaFuncAttributeMaxDynamicSharedMemorySize, SM_G2);
    cudaFuncSetAttribute(lse_hmma_k, cudaFuncAttributeMaxDynamicSharedMemorySize, SM_L);

    // prep
    cvt_k<<<1024, 256>>>(features, fhi, (size_t)MB * DD);
    tsplit_k<<<dim3(HH / 32, DD / 32), dim3(32, 8)>>>(w1, w1hi, nullptr, DD, HH);
    tsplit_k<<<dim3(FF / 32, HH / 32), dim3(32, 8)>>>(w2, w2hi, w2lo, HH, FF);

    // 1) h = relu(features @ w1 + b1)
    hgemm1_k<<<dim3(HH / 128, MB / 128), 256, SM_G1>>>(fhi, w1hi, b1, HH, hhi);

    // 2) p = h @ w2 + b2, fused L2-normalize (64-row tiles, full chip)
    float* outz = (out_size >= 1 + MB * FF) ? (out + 1) : nullptr;
    hgemm2_k<<<dim3(1, MB / 64), 256, SM_G2>>>(hhi, w2hi, w2lo, b2, z, zhi, outz);

    // 3) pos, 4) masked exp-sums (MUFU exp), 5) loss
    pos_k<<<MB, 128>>>(z, posb);
    lse_hmma_k<<<dim3(2, MB / 128), 256, SM_L>>>(zhi, psb);
    loss_k<<<1, 256>>>(psb, posb, out);
}